// round 12
// baseline (speedup 1.0000x reference)
#include <cuda_runtime.h>
#include <cuda_bf16.h>
#include <cstdint>

#define U_NUM 30000
#define NTOT  100000

typedef unsigned long long u64;
typedef unsigned int u32;

// ---------------- scratch (device globals; allocation-free) ----------------
__device__ __align__(256) float g_H0[(size_t)NTOT * 128];
__device__ __align__(256) float g_F1[(size_t)NTOT * 128];
__device__ __align__(256) float g_H1[(size_t)NTOT * 64];
__device__ __align__(256) float g_F2[(size_t)NTOT * 64];
// fragment-packed bf16 weights: uint4 = {hi01, hi23, lo01, lo23} per [ks][nt][lane]
__device__ __align__(256) uint4 g_w10f[16 * 16 * 32];
__device__ __align__(256) uint4 g_w20f[16 * 16 * 32];
__device__ __align__(256) uint4 g_w11f[8 * 8 * 32];
__device__ __align__(256) uint4 g_w21f[8 * 8 * 32];
__device__ __align__(256) uint4 g_t1f[56 * 8 * 32];

// ---------------- helpers ----------------
__device__ __forceinline__ u32 smem_u32(const void* p) {
    u32 a;
    asm("{ .reg .u64 t; cvta.to.shared.u64 t, %1; cvt.u32.u64 %0, t; }" : "=r"(a) : "l"(p));
    return a;
}
__device__ __forceinline__ void ldm4(u32* r, u32 addr) {
    asm volatile("ldmatrix.sync.aligned.m8n8.x4.shared.b16 {%0,%1,%2,%3}, [%4];"
                 : "=r"(r[0]), "=r"(r[1]), "=r"(r[2]), "=r"(r[3]) : "r"(addr));
}
__device__ __forceinline__ void mma16816(float* c, const u32* a, u32 b0, u32 b1) {
    asm volatile("mma.sync.aligned.m16n8k16.row.col.f32.bf16.bf16.f32 "
                 "{%0,%1,%2,%3}, {%4,%5,%6,%7}, {%8,%9}, {%0,%1,%2,%3};"
                 : "+f"(c[0]), "+f"(c[1]), "+f"(c[2]), "+f"(c[3])
                 : "r"(a[0]), "r"(a[1]), "r"(a[2]), "r"(a[3]), "r"(b0), "r"(b1));
}
__device__ __forceinline__ void split2(float a, float b, u32& hi, u32& lo) {
    __nv_bfloat162 h = __floats2bfloat162_rn(a, b);
    float2 hf = __bfloat1622float2(h);
    __nv_bfloat162 l = __floats2bfloat162_rn(a - hf.x, b - hf.y);
    hi = *reinterpret_cast<u32*>(&h);
    lo = *reinterpret_cast<u32*>(&l);
}
__device__ __forceinline__ u32 sq_bf16x2(u32 x) {
    __nv_bfloat162 h = *reinterpret_cast<__nv_bfloat162*>(&x);
    __nv_bfloat162 s = __hmul2(h, h);
    return *reinterpret_cast<u32*>(&s);
}
__device__ __forceinline__ void red4(float* p, float a, float b, float c, float d) {
    asm volatile("{ .reg .u64 q; cvta.to.global.u64 q, %0; red.global.add.v4.f32 [q], {%1,%2,%3,%4}; }"
                 :: "l"(p), "f"(a), "f"(b), "f"(c), "f"(d) : "memory");
}

// ============================================================================
// Weight fragment prep
// ============================================================================
__device__ __forceinline__ void pack_frag(const float* __restrict__ W, uint4* __restrict__ dst,
                                          int ks, int nt, int lane, int NT, int K)
{
    int n = nt * 8 + (lane >> 2);
    int k = ks * 16 + (lane & 3) * 2;
    const float* p = W + (size_t)n * K + k;
    float x0 = p[0], x1 = p[1], x2 = p[8], x3 = p[9];
    u32 h01, l01, h23, l23;
    split2(x0, x1, h01, l01);
    split2(x2, x3, h23, l23);
    dst[((size_t)ks * NT + nt) * 32 + lane] = make_uint4(h01, h23, l01, l23);
}

__global__ void k_prep(const float* __restrict__ W10, const float* __restrict__ W20,
                       const float* __restrict__ W11, const float* __restrict__ W21,
                       const float* __restrict__ T1W)
{
    int i = blockIdx.x * 256 + threadIdx.x;
    if (i < 8192) {                        // layer0: KS=16, NT=16
        int lane = i & 31, nt = (i >> 5) & 15, ks = i >> 9;
        pack_frag(W10, g_w10f, ks, nt, lane, 16, 256);
        pack_frag(W20, g_w20f, ks, nt, lane, 16, 256);
    } else if (i < 10240) {                // layer1: KS=8, NT=8
        int j = i - 8192;
        int lane = j & 31, nt = (j >> 5) & 7, ks = j >> 8;
        pack_frag(W11, g_w11f, ks, nt, lane, 8, 128);
        pack_frag(W21, g_w21f, ks, nt, lane, 8, 128);
    } else if (i < 24576) {                // T1: KS=56, NT=8
        int j = i - 10240;
        int lane = j & 31, nt = (j >> 5) & 7, ks = j >> 8;
        pack_frag(T1W, g_t1f, ks, nt, lane, 8, 896);
    }
}

// ============================================================================
// Fused dual GEMM: main path bf16x3 compensated; square path's A fragment
// derived in registers (HMUL2 of the hi fragment).
//   Fout = A@W1^T + (b1+b2),  Hout = A@W1^T + (A*A)@W2^T
// ============================================================================
template<int THREADS, int OCC, int BM, int DOUT, int KTOT, int CHUNK,
         int MODE, int WM_N, int WN_N>
__global__ __launch_bounds__(THREADS, OCC) void k_gemm_mma(
    const float* __restrict__ uE, const float* __restrict__ iE,
    const float* __restrict__ b1, const float* __restrict__ b2)
{
    constexpr int SR = CHUNK + 8;
    constexpr int ABUF = BM * SR;
    constexpr int NCH = KTOT / CHUNK;
    constexpr int KS_C = CHUNK / 16;
    constexpr int NT = DOUT / 8;
    constexpr int JW = NT / WN_N;
    constexpr int F4R = CHUNK / 4;
    extern __shared__ __align__(16) char smem[];
    __nv_bfloat16* sA = (__nv_bfloat16*)smem;
    const u32 sbase = smem_u32(smem);

    const uint4* __restrict__ w1f = (MODE == 0) ? g_w10f : g_w11f;
    const uint2* __restrict__ w2f = (MODE == 0) ? (const uint2*)g_w20f : (const uint2*)g_w21f;
    float* __restrict__ Fout = (MODE == 0) ? g_F1 : g_F2;
    float* __restrict__ Hout = (MODE == 0) ? g_H0 : g_H1;

    const int t = threadIdx.x, wid = t >> 5, lane = t & 31;
    const int wm = wid / WN_N, wn = wid % WN_N;
    const int row0 = blockIdx.x * BM;

    float acc1[2][JW][4], acc2[2][JW][4];
#pragma unroll
    for (int mt = 0; mt < 2; mt++)
#pragma unroll
        for (int j = 0; j < JW; j++)
#pragma unroll
            for (int q = 0; q < 4; q++) { acc1[mt][j][q] = 0.f; acc2[mt][j][q] = 0.f; }

    const int arow = lane & 15;
    const int kshift = (lane >> 4) * 8;

    for (int ch = 0; ch < NCH; ch++) {
        __syncthreads();
#pragma unroll
        for (int it = 0; it < BM * F4R / THREADS; it++) {
            int fid = t + it * THREADS;
            int r = fid / F4R;
            int c4 = (fid % F4R) * 4;
            int gr = row0 + r;
            float4 v = make_float4(0.f, 0.f, 0.f, 0.f);
            if (gr < NTOT) {
                const float* src;
                if (MODE == 0) src = (gr < U_NUM) ? uE + (size_t)gr * 256
                                                  : iE + (size_t)(gr - U_NUM) * 256;
                else           src = g_F1 + (size_t)gr * 128;
                v = *(const float4*)(src + ch * CHUNK + c4);
            }
            u32 h01, l01, h23, l23;
            split2(v.x, v.y, h01, l01);
            split2(v.z, v.w, h23, l23);
            int off = r * SR + c4;
            *(uint2*)(sA + off)        = make_uint2(h01, h23);
            *(uint2*)(sA + ABUF + off) = make_uint2(l01, l23);
        }
        __syncthreads();

#pragma unroll 2
        for (int ks2 = 0; ks2 < KS_C; ks2++) {
            const int ks = ch * KS_C + ks2;
            u32 a[2][2][4];
#pragma unroll
            for (int v = 0; v < 2; v++)
#pragma unroll
                for (int mt = 0; mt < 2; mt++) {
                    int row = wm * 32 + mt * 16 + arow;
                    u32 addr = sbase + (u32)((v * ABUF + row * SR + ks2 * 16 + kshift) * 2);
                    ldm4(a[v][mt], addr);
                }
            u32 asq[2][4];
#pragma unroll
            for (int mt = 0; mt < 2; mt++)
#pragma unroll
                for (int i = 0; i < 4; i++)
                    asq[mt][i] = sq_bf16x2(a[0][mt][i]);

#pragma unroll
            for (int h = 0; h < (JW + 1) / 2; h++) {
                constexpr int JH = (JW >= 2) ? 2 : 1;
                uint4 bw1[JH];
                uint2 bw2[JH];
#pragma unroll
                for (int jj = 0; jj < JH; jj++) {
                    int nt = wn * JW + h * JH + jj;
                    u32 idx = ((u32)(ks * NT + nt)) * 32 + lane;
                    bw1[jj] = __ldg(w1f + idx);
                    bw2[jj] = __ldg(w2f + (size_t)idx * 2);
                }
#pragma unroll
                for (int mt = 0; mt < 2; mt++)
#pragma unroll
                    for (int jj = 0; jj < JH; jj++) {
                        int j = h * JH + jj;
                        mma16816(acc1[mt][j], a[0][mt], bw1[jj].x, bw1[jj].y);
                        mma16816(acc1[mt][j], a[0][mt], bw1[jj].z, bw1[jj].w);
                        mma16816(acc1[mt][j], a[1][mt], bw1[jj].x, bw1[jj].y);
                        mma16816(acc2[mt][j], asq[mt],  bw2[jj].x, bw2[jj].y);
                    }
            }
        }
    }

    const int r_base = row0 + wm * 32 + (lane >> 2);
    const int c_base = wn * (JW * 8) + (lane & 3) * 2;
#pragma unroll
    for (int mt = 0; mt < 2; mt++)
#pragma unroll
        for (int j = 0; j < JW; j++) {
            int c = c_base + j * 8;
            float bs0 = __ldg(b1 + c) + __ldg(b2 + c);
            float bs1 = __ldg(b1 + c + 1) + __ldg(b2 + c + 1);
#pragma unroll
            for (int half = 0; half < 2; half++) {
                int r = r_base + mt * 16 + half * 8;
                if (r < NTOT) {
                    float a0 = acc1[mt][j][half * 2], a1 = acc1[mt][j][half * 2 + 1];
                    float2 f = make_float2(a0 + bs0, a1 + bs1);
                    float2 h2 = make_float2(a0 + acc2[mt][j][half * 2],
                                            a1 + acc2[mt][j][half * 2 + 1]);
                    *(float2*)(Fout + (size_t)r * DOUT + c) = f;
                    *(float2*)(Hout + (size_t)r * DOUT + c) = h2;
                }
            }
        }
}

// ============================================================================
// SpMM scatter: F[row] += val * H[col].  8 edges per (sub)warp.
// ============================================================================
__global__ void k_spmm128(const int* __restrict__ er, const int* __restrict__ ec,
                          const float* __restrict__ ev, int nnz)
{
    int w = (blockIdx.x * blockDim.x + threadIdx.x) >> 5;
    int lane = threadIdx.x & 31;
    int e0 = w * 8;
    if (e0 >= nnz) return;
    if (e0 + 8 <= nnz) {
        int4 ra = *(const int4*)(er + e0), rb = *(const int4*)(er + e0 + 4);
        int4 ca = *(const int4*)(ec + e0), cb = *(const int4*)(ec + e0 + 4);
        float4 va = *(const float4*)(ev + e0), vb = *(const float4*)(ev + e0 + 4);
        int rr[8] = {ra.x, ra.y, ra.z, ra.w, rb.x, rb.y, rb.z, rb.w};
        int cc[8] = {ca.x, ca.y, ca.z, ca.w, cb.x, cb.y, cb.z, cb.w};
        float vv[8] = {va.x, va.y, va.z, va.w, vb.x, vb.y, vb.z, vb.w};
        float4 x[8];
#pragma unroll
        for (int i = 0; i < 8; i++)
            x[i] = *(const float4*)(g_H0 + (size_t)cc[i] * 128 + lane * 4);
#pragma unroll
        for (int i = 0; i < 8; i++)
            red4(g_F1 + (size_t)rr[i] * 128 + lane * 4,
                 vv[i] * x[i].x, vv[i] * x[i].y, vv[i] * x[i].z, vv[i] * x[i].w);
    } else {
        for (int e = e0; e < nnz; e++) {
            int r = __ldg(er + e), c = __ldg(ec + e);
            float v = __ldg(ev + e);
            float4 x = *(const float4*)(g_H0 + (size_t)c * 128 + lane * 4);
            red4(g_F1 + (size_t)r * 128 + lane * 4, v * x.x, v * x.y, v * x.z, v * x.w);
        }
    }
}

__global__ void k_spmm64(const int* __restrict__ er, const int* __restrict__ ec,
                         const float* __restrict__ ev, int nnz)
{
    int idx = blockIdx.x * blockDim.x + threadIdx.x;
    int hw = idx >> 4;
    int l = idx & 15;
    int e0 = hw * 8;
    if (e0 >= nnz) return;
    if (e0 + 8 <= nnz) {
        int4 ra = *(const int4*)(er + e0), rb = *(const int4*)(er + e0 + 4);
        int4 ca = *(const int4*)(ec + e0), cb = *(const int4*)(ec + e0 + 4);
        float4 va = *(const float4*)(ev + e0), vb = *(const float4*)(ev + e0 + 4);
        int rr[8] = {ra.x, ra.y, ra.z, ra.w, rb.x, rb.y, rb.z, rb.w};
        int cc[8] = {ca.x, ca.y, ca.z, ca.w, cb.x, cb.y, cb.z, cb.w};
        float vv[8] = {va.x, va.y, va.z, va.w, vb.x, vb.y, vb.z, vb.w};
        float4 x[8];
#pragma unroll
        for (int i = 0; i < 8; i++)
            x[i] = *(const float4*)(g_H1 + (size_t)cc[i] * 64 + l * 4);
#pragma unroll
        for (int i = 0; i < 8; i++)
            red4(g_F2 + (size_t)rr[i] * 64 + l * 4,
                 vv[i] * x[i].x, vv[i] * x[i].y, vv[i] * x[i].z, vv[i] * x[i].w);
    } else {
        for (int e = e0; e < nnz; e++) {
            int r = __ldg(er + e), c = __ldg(ec + e);
            float v = __ldg(ev + e);
            float4 x = *(const float4*)(g_H1 + (size_t)c * 64 + l * 4);
            red4(g_F2 + (size_t)r * 64 + l * 4, v * x.x, v * x.y, v * x.z, v * x.w);
        }
    }
}

// ============================================================================
// Fused MLP head: layer1 (896->64) bf16x3 mma (CHUNK=112, OCC=3), layers 2/3 FFMA.
// ============================================================================
__global__ __launch_bounds__(256, 3) void k_mlp_mma(
    const int* __restrict__ uIdx, const int* __restrict__ itIdx,
    const float* __restrict__ uE, const float* __restrict__ iE,
    const float* __restrict__ T1b,
    const float* __restrict__ T2W, const float* __restrict__ T2b,
    const float* __restrict__ T3W, const float* __restrict__ T3b,
    float* __restrict__ out, int B)
{
    constexpr int SR = 120;                 // 112 + 8 pad (bf16)
    constexpr int ABUF = 64 * SR;           // 7680 elements per variant
    constexpr int OFF_SU = 2 * ABUF * 2;    // 30720
    constexpr int OFF_SI = OFF_SU + 256;
    constexpr int HSR = 65;
    constexpr int OFF_T2 = 64 * HSR * 4 + 64;     // 16704
    constexpr int OFF_PART = OFF_T2 + 32 * 64 * 4;
    extern __shared__ __align__(16) char smem[];
    __nv_bfloat16* sA = (__nv_bfloat16*)smem;
    const u32 sbase = smem_u32(smem);
    int* su = (int*)(smem + OFF_SU);
    int* si = (int*)(smem + OFF_SI);

    const int t = threadIdx.x, wid = t >> 5, lane = t & 31;
    const int wm = wid >> 2, wn = wid & 3;
    const int rb = blockIdx.x * 64;

    if (t < 64) {
        int br = rb + t;
        su[t] = (br < B) ? uIdx[br] : 0;
        si[t] = (br < B) ? itIdx[br] : 0;
    }

    float acc[2][2][4];
#pragma unroll
    for (int mt = 0; mt < 2; mt++)
#pragma unroll
        for (int j = 0; j < 2; j++)
#pragma unroll
            for (int q = 0; q < 4; q++) acc[mt][j][q] = 0.f;

    const int arow = lane & 15;
    const int kshift = (lane >> 4) * 8;

    for (int chunk = 0; chunk < 8; chunk++) {
        const int kb = chunk * 112;
        __syncthreads();
#pragma unroll
        for (int it = 0; it < 7; it++) {
            int fid = t + it * 256;
            int r = fid / 28;
            int c4 = (fid % 28) * 4;
            int kg = kb + c4;
            const float* src; int stride, off, rowi;
            if (kg < 256)      { src = uE;   stride = 256; off = kg;       rowi = su[r]; }
            else if (kg < 384) { src = g_F1; stride = 128; off = kg - 256; rowi = su[r]; }
            else if (kg < 448) { src = g_F2; stride = 64;  off = kg - 384; rowi = su[r]; }
            else if (kg < 704) { src = iE;   stride = 256; off = kg - 448; rowi = si[r]; }
            else if (kg < 832) { src = g_F1; stride = 128; off = kg - 704; rowi = si[r] + U_NUM; }
            else               { src = g_F2; stride = 64;  off = kg - 832; rowi = si[r] + U_NUM; }
            float4 v = *(const float4*)(src + (size_t)rowi * stride + off);
            u32 h01, l01, h23, l23;
            split2(v.x, v.y, h01, l01);
            split2(v.z, v.w, h23, l23);
            int so = r * SR + c4;
            *(uint2*)(sA + so)        = make_uint2(h01, h23);
            *(uint2*)(sA + ABUF + so) = make_uint2(l01, l23);
        }
        __syncthreads();

#pragma unroll
        for (int ks2 = 0; ks2 < 7; ks2++) {
            const int ks = chunk * 7 + ks2;
            uint4 bw[2];
#pragma unroll
            for (int j = 0; j < 2; j++) {
                int nt = wn * 2 + j;
                bw[j] = __ldg(g_t1f + ((u32)(ks * 8 + nt)) * 32 + lane);
            }
            u32 a[2][2][4];
#pragma unroll
            for (int v = 0; v < 2; v++)
#pragma unroll
                for (int mt = 0; mt < 2; mt++) {
                    int row = wm * 32 + mt * 16 + arow;
                    u32 addr = sbase + (u32)((v * ABUF + row * SR + ks2 * 16 + kshift) * 2);
                    ldm4(a[v][mt], addr);
                }
#pragma unroll
            for (int mt = 0; mt < 2; mt++)
#pragma unroll
                for (int j = 0; j < 2; j++) {
                    mma16816(acc[mt][j], a[0][mt], bw[j].x, bw[j].y);
                    mma16816(acc[mt][j], a[0][mt], bw[j].z, bw[j].w);
                    mma16816(acc[mt][j], a[1][mt], bw[j].x, bw[j].y);
                }
        }
    }
    __syncthreads();

    float* Hs = (float*)smem;
    float* T2s = (float*)(smem + OFF_T2);
    float* part = (float*)(smem + OFF_PART);
    {
        const int rr = wm * 32 + (lane >> 2);
        const int cc = wn * 16 + (lane & 3) * 2;
#pragma unroll
        for (int mt = 0; mt < 2; mt++)
#pragma unroll
            for (int j = 0; j < 2; j++) {
                int c = cc + j * 8;
                float tb0 = __ldg(T1b + c), tb1 = __ldg(T1b + c + 1);
#pragma unroll
                for (int half = 0; half < 2; half++) {
                    int r = rr + mt * 16 + half * 8;
                    Hs[r * HSR + c]     = fmaxf(acc[mt][j][half * 2] + tb0, 0.f);
                    Hs[r * HSR + c + 1] = fmaxf(acc[mt][j][half * 2 + 1] + tb1, 0.f);
                }
            }
    }
#pragma unroll
    for (int i = 0; i < 2; i++) {
        int idx = t + i * 256;
        ((float4*)T2s)[idx] = ((const float4*)T2W)[idx];
    }
    __syncthreads();

    {
        int r = t & 63, g = t >> 6;
        float p = 0.f;
#pragma unroll
        for (int j = 0; j < 8; j++) {
            int c2 = g * 8 + j;
            float s = T2b[c2];
#pragma unroll
            for (int k = 0; k < 64; k++) s += Hs[r * HSR + k] * T2s[c2 * 64 + k];
            p += fmaxf(s, 0.f) * T3W[c2];
        }
        part[g * 64 + r] = p;
    }
    __syncthreads();
    if (t < 64) {
        int br = rb + t;
        if (br < B)
            out[br] = part[t] + part[64 + t] + part[128 + t] + part[192 + t] + T3b[0];
    }
}

// ============================================================================
extern "C" void kernel_launch(void* const* d_in, const int* in_sizes, int n_in,
                              void* d_out, int out_size)
{
    const int*   userIdx = (const int*)d_in[0];
    const int*   itemIdx = (const int*)d_in[1];
    const int*   er      = (const int*)d_in[2];
    const int*   ec      = (const int*)d_in[3];
    const float* ev      = (const float*)d_in[4];
    const float* uE      = (const float*)d_in[5];
    const float* iE      = (const float*)d_in[6];
    const float* W1_0    = (const float*)d_in[7];
    const float* b1_0    = (const float*)d_in[8];
    const float* W2_0    = (const float*)d_in[9];
    const float* b2_0    = (const float*)d_in[10];
    const float* W1_1    = (const float*)d_in[11];
    const float* b1_1    = (const float*)d_in[12];
    const float* W2_1    = (const float*)d_in[13];
    const float* b2_1    = (const float*)d_in[14];
    const float* T1W     = (const float*)d_in[15];
    const float* T1b     = (const float*)d_in[16];
    const float* T2W     = (const float*)d_in[17];
    const float* T2b     = (const float*)d_in[18];
    const float* T3W     = (const float*)d_in[19];
    const float* T3b     = (const float*)d_in[20];
    float* out = (float*)d_out;

    const int B   = in_sizes[0];
    const int nnz = in_sizes[2];

    constexpr int SMEM0 = 2 * 64 * (128 + 8) * 2;    // 34816, OCC=2
    constexpr int SMEM1 = 2 * 64 * (64 + 8) * 2;     // 18432, OCC=6
    constexpr int SMEMM = 2 * 64 * 120 * 2 + 1024;   // 31744, OCC=3
    static bool attr_done = false;
    if (!attr_done) {
        cudaFuncSetAttribute((const void*)k_gemm_mma<256, 2, 64, 128, 256, 128, 0, 2, 4>,
                             cudaFuncAttributeMaxDynamicSharedMemorySize, SMEM0);
        cudaFuncSetAttribute((const void*)k_gemm_mma<128, 6, 64, 64, 128, 64, 1, 2, 2>,
                             cudaFuncAttributeMaxDynamicSharedMemorySize, SMEM1);
        cudaFuncSetAttribute((const void*)k_mlp_mma,
                             cudaFuncAttributeMaxDynamicSharedMemorySize, SMEMM);
        attr_done = true;
    }

    k_prep<<<96, 256>>>(W1_0, W2_0, W1_1, W2_1, T1W);

    k_gemm_mma<256, 2, 64, 128, 256, 128, 0, 2, 4>
        <<<(NTOT + 63) / 64, 256, SMEM0>>>(uE, iE, b1_0, b2_0);

    {
        long long warps = ((long long)nnz + 7) / 8;
        int blocks = (int)((warps * 32 + 255) / 256);
        k_spmm128<<<blocks, 256>>>(er, ec, ev, nnz);
    }

    k_gemm_mma<128, 6, 64, 64, 128, 64, 1, 2, 2>
        <<<(NTOT + 63) / 64, 128, SMEM1>>>(uE, iE, b1_1, b2_1);

    {
        long long hws = ((long long)nnz + 7) / 8;
        int blocks = (int)((hws * 16 + 255) / 256);
        k_spmm64<<<blocks, 256>>>(er, ec, ev, nnz);
    }

    k_mlp_mma<<<(B + 63) / 64, 256, SMEMM>>>(userIdx, itemIdx, uE, iE,
                                             T1b, T2W, T2b, T3W, T3b, out, B);
}

// round 13
// speedup vs baseline: 1.0489x; 1.0489x over previous
#include <cuda_runtime.h>
#include <cuda_bf16.h>
#include <cstdint>

#define U_NUM 30000
#define NTOT  100000

typedef unsigned long long u64;
typedef unsigned int u32;

// ---------------- scratch (device globals; allocation-free) ----------------
__device__ __align__(256) float g_H0[(size_t)NTOT * 128];
__device__ __align__(256) float g_F1[(size_t)NTOT * 128];
__device__ __align__(256) float g_H1[(size_t)NTOT * 64];
__device__ __align__(256) float g_F2[(size_t)NTOT * 64];
// fragment-packed bf16 weights: uint4 = {hi01, hi23, lo01, lo23} per [ks][nt][lane]
__device__ __align__(256) uint4 g_w10f[16 * 16 * 32];
__device__ __align__(256) uint4 g_w20f[16 * 16 * 32];
__device__ __align__(256) uint4 g_w11f[8 * 8 * 32];
__device__ __align__(256) uint4 g_w21f[8 * 8 * 32];
__device__ __align__(256) uint4 g_t1f[56 * 8 * 32];

// ---------------- helpers ----------------
__device__ __forceinline__ u32 smem_u32(const void* p) {
    u32 a;
    asm("{ .reg .u64 t; cvta.to.shared.u64 t, %1; cvt.u32.u64 %0, t; }" : "=r"(a) : "l"(p));
    return a;
}
__device__ __forceinline__ void ldm4(u32* r, u32 addr) {
    asm volatile("ldmatrix.sync.aligned.m8n8.x4.shared.b16 {%0,%1,%2,%3}, [%4];"
                 : "=r"(r[0]), "=r"(r[1]), "=r"(r[2]), "=r"(r[3]) : "r"(addr));
}
__device__ __forceinline__ void mma16816(float* c, const u32* a, u32 b0, u32 b1) {
    asm volatile("mma.sync.aligned.m16n8k16.row.col.f32.bf16.bf16.f32 "
                 "{%0,%1,%2,%3}, {%4,%5,%6,%7}, {%8,%9}, {%0,%1,%2,%3};"
                 : "+f"(c[0]), "+f"(c[1]), "+f"(c[2]), "+f"(c[3])
                 : "r"(a[0]), "r"(a[1]), "r"(a[2]), "r"(a[3]), "r"(b0), "r"(b1));
}
__device__ __forceinline__ void split2(float a, float b, u32& hi, u32& lo) {
    __nv_bfloat162 h = __floats2bfloat162_rn(a, b);
    float2 hf = __bfloat1622float2(h);
    __nv_bfloat162 l = __floats2bfloat162_rn(a - hf.x, b - hf.y);
    hi = *reinterpret_cast<u32*>(&h);
    lo = *reinterpret_cast<u32*>(&l);
}
__device__ __forceinline__ u32 sq_bf16x2(u32 x) {
    __nv_bfloat162 h = *reinterpret_cast<__nv_bfloat162*>(&x);
    __nv_bfloat162 s = __hmul2(h, h);
    return *reinterpret_cast<u32*>(&s);
}
__device__ __forceinline__ void red4(float* p, float a, float b, float c, float d) {
    asm volatile("{ .reg .u64 q; cvta.to.global.u64 q, %0; red.global.add.v4.f32 [q], {%1,%2,%3,%4}; }"
                 :: "l"(p), "f"(a), "f"(b), "f"(c), "f"(d) : "memory");
}

// ============================================================================
// Weight fragment prep
// ============================================================================
__device__ __forceinline__ void pack_frag(const float* __restrict__ W, uint4* __restrict__ dst,
                                          int ks, int nt, int lane, int NT, int K)
{
    int n = nt * 8 + (lane >> 2);
    int k = ks * 16 + (lane & 3) * 2;
    const float* p = W + (size_t)n * K + k;
    float x0 = p[0], x1 = p[1], x2 = p[8], x3 = p[9];
    u32 h01, l01, h23, l23;
    split2(x0, x1, h01, l01);
    split2(x2, x3, h23, l23);
    dst[((size_t)ks * NT + nt) * 32 + lane] = make_uint4(h01, h23, l01, l23);
}

__global__ void k_prep(const float* __restrict__ W10, const float* __restrict__ W20,
                       const float* __restrict__ W11, const float* __restrict__ W21,
                       const float* __restrict__ T1W)
{
    int i = blockIdx.x * 256 + threadIdx.x;
    if (i < 8192) {                        // layer0: KS=16, NT=16
        int lane = i & 31, nt = (i >> 5) & 15, ks = i >> 9;
        pack_frag(W10, g_w10f, ks, nt, lane, 16, 256);
        pack_frag(W20, g_w20f, ks, nt, lane, 16, 256);
    } else if (i < 10240) {                // layer1: KS=8, NT=8
        int j = i - 8192;
        int lane = j & 31, nt = (j >> 5) & 7, ks = j >> 8;
        pack_frag(W11, g_w11f, ks, nt, lane, 8, 128);
        pack_frag(W21, g_w21f, ks, nt, lane, 8, 128);
    } else if (i < 24576) {                // T1: KS=56, NT=8
        int j = i - 10240;
        int lane = j & 31, nt = (j >> 5) & 7, ks = j >> 8;
        pack_frag(T1W, g_t1f, ks, nt, lane, 8, 896);
    }
}

// ============================================================================
// Fused dual GEMM: main path bf16x3 compensated; square path's A fragment
// derived in registers (HMUL2 of the hi fragment).
//   Fout = A@W1^T + (b1+b2),  Hout = A@W1^T + (A*A)@W2^T
// ============================================================================
template<int THREADS, int OCC, int BM, int DOUT, int KTOT, int CHUNK,
         int MODE, int WM_N, int WN_N>
__global__ __launch_bounds__(THREADS, OCC) void k_gemm_mma(
    const float* __restrict__ uE, const float* __restrict__ iE,
    const float* __restrict__ b1, const float* __restrict__ b2)
{
    constexpr int SR = CHUNK + 8;
    constexpr int ABUF = BM * SR;
    constexpr int NCH = KTOT / CHUNK;
    constexpr int KS_C = CHUNK / 16;
    constexpr int NT = DOUT / 8;
    constexpr int JW = NT / WN_N;
    constexpr int F4R = CHUNK / 4;
    extern __shared__ __align__(16) char smem[];
    __nv_bfloat16* sA = (__nv_bfloat16*)smem;
    const u32 sbase = smem_u32(smem);

    const uint4* __restrict__ w1f = (MODE == 0) ? g_w10f : g_w11f;
    const uint2* __restrict__ w2f = (MODE == 0) ? (const uint2*)g_w20f : (const uint2*)g_w21f;
    float* __restrict__ Fout = (MODE == 0) ? g_F1 : g_F2;
    float* __restrict__ Hout = (MODE == 0) ? g_H0 : g_H1;

    const int t = threadIdx.x, wid = t >> 5, lane = t & 31;
    const int wm = wid / WN_N, wn = wid % WN_N;
    const int row0 = blockIdx.x * BM;

    float acc1[2][JW][4], acc2[2][JW][4];
#pragma unroll
    for (int mt = 0; mt < 2; mt++)
#pragma unroll
        for (int j = 0; j < JW; j++)
#pragma unroll
            for (int q = 0; q < 4; q++) { acc1[mt][j][q] = 0.f; acc2[mt][j][q] = 0.f; }

    const int arow = lane & 15;
    const int kshift = (lane >> 4) * 8;

    for (int ch = 0; ch < NCH; ch++) {
        __syncthreads();
#pragma unroll
        for (int it = 0; it < BM * F4R / THREADS; it++) {
            int fid = t + it * THREADS;
            int r = fid / F4R;
            int c4 = (fid % F4R) * 4;
            int gr = row0 + r;
            float4 v = make_float4(0.f, 0.f, 0.f, 0.f);
            if (gr < NTOT) {
                const float* src;
                if (MODE == 0) src = (gr < U_NUM) ? uE + (size_t)gr * 256
                                                  : iE + (size_t)(gr - U_NUM) * 256;
                else           src = g_F1 + (size_t)gr * 128;
                v = *(const float4*)(src + ch * CHUNK + c4);
            }
            u32 h01, l01, h23, l23;
            split2(v.x, v.y, h01, l01);
            split2(v.z, v.w, h23, l23);
            int off = r * SR + c4;
            *(uint2*)(sA + off)        = make_uint2(h01, h23);
            *(uint2*)(sA + ABUF + off) = make_uint2(l01, l23);
        }
        __syncthreads();

#pragma unroll 2
        for (int ks2 = 0; ks2 < KS_C; ks2++) {
            const int ks = ch * KS_C + ks2;
            u32 a[2][2][4];
#pragma unroll
            for (int v = 0; v < 2; v++)
#pragma unroll
                for (int mt = 0; mt < 2; mt++) {
                    int row = wm * 32 + mt * 16 + arow;
                    u32 addr = sbase + (u32)((v * ABUF + row * SR + ks2 * 16 + kshift) * 2);
                    ldm4(a[v][mt], addr);
                }
            u32 asq[2][4];
#pragma unroll
            for (int mt = 0; mt < 2; mt++)
#pragma unroll
                for (int i = 0; i < 4; i++)
                    asq[mt][i] = sq_bf16x2(a[0][mt][i]);

#pragma unroll
            for (int h = 0; h < (JW + 1) / 2; h++) {
                constexpr int JH = (JW >= 2) ? 2 : 1;
                uint4 bw1[JH];
                uint2 bw2[JH];
#pragma unroll
                for (int jj = 0; jj < JH; jj++) {
                    int nt = wn * JW + h * JH + jj;
                    u32 idx = ((u32)(ks * NT + nt)) * 32 + lane;
                    bw1[jj] = __ldg(w1f + idx);
                    bw2[jj] = __ldg(w2f + (size_t)idx * 2);
                }
#pragma unroll
                for (int mt = 0; mt < 2; mt++)
#pragma unroll
                    for (int jj = 0; jj < JH; jj++) {
                        int j = h * JH + jj;
                        mma16816(acc1[mt][j], a[0][mt], bw1[jj].x, bw1[jj].y);
                        mma16816(acc1[mt][j], a[0][mt], bw1[jj].z, bw1[jj].w);
                        mma16816(acc1[mt][j], a[1][mt], bw1[jj].x, bw1[jj].y);
                        mma16816(acc2[mt][j], asq[mt],  bw2[jj].x, bw2[jj].y);
                    }
            }
        }
    }

    const int r_base = row0 + wm * 32 + (lane >> 2);
    const int c_base = wn * (JW * 8) + (lane & 3) * 2;
#pragma unroll
    for (int mt = 0; mt < 2; mt++)
#pragma unroll
        for (int j = 0; j < JW; j++) {
            int c = c_base + j * 8;
            float bs0 = __ldg(b1 + c) + __ldg(b2 + c);
            float bs1 = __ldg(b1 + c + 1) + __ldg(b2 + c + 1);
#pragma unroll
            for (int half = 0; half < 2; half++) {
                int r = r_base + mt * 16 + half * 8;
                if (r < NTOT) {
                    float a0 = acc1[mt][j][half * 2], a1 = acc1[mt][j][half * 2 + 1];
                    float2 f = make_float2(a0 + bs0, a1 + bs1);
                    float2 h2 = make_float2(a0 + acc2[mt][j][half * 2],
                                            a1 + acc2[mt][j][half * 2 + 1]);
                    *(float2*)(Fout + (size_t)r * DOUT + c) = f;
                    *(float2*)(Hout + (size_t)r * DOUT + c) = h2;
                }
            }
        }
}

// ============================================================================
// SpMM scatter: F[row] += val * H[col].  8 edges per (sub)warp.
// ============================================================================
__global__ void k_spmm128(const int* __restrict__ er, const int* __restrict__ ec,
                          const float* __restrict__ ev, int nnz)
{
    int w = (blockIdx.x * blockDim.x + threadIdx.x) >> 5;
    int lane = threadIdx.x & 31;
    int e0 = w * 8;
    if (e0 >= nnz) return;
    if (e0 + 8 <= nnz) {
        int4 ra = *(const int4*)(er + e0), rb = *(const int4*)(er + e0 + 4);
        int4 ca = *(const int4*)(ec + e0), cb = *(const int4*)(ec + e0 + 4);
        float4 va = *(const float4*)(ev + e0), vb = *(const float4*)(ev + e0 + 4);
        int rr[8] = {ra.x, ra.y, ra.z, ra.w, rb.x, rb.y, rb.z, rb.w};
        int cc[8] = {ca.x, ca.y, ca.z, ca.w, cb.x, cb.y, cb.z, cb.w};
        float vv[8] = {va.x, va.y, va.z, va.w, vb.x, vb.y, vb.z, vb.w};
        float4 x[8];
#pragma unroll
        for (int i = 0; i < 8; i++)
            x[i] = *(const float4*)(g_H0 + (size_t)cc[i] * 128 + lane * 4);
#pragma unroll
        for (int i = 0; i < 8; i++)
            red4(g_F1 + (size_t)rr[i] * 128 + lane * 4,
                 vv[i] * x[i].x, vv[i] * x[i].y, vv[i] * x[i].z, vv[i] * x[i].w);
    } else {
        for (int e = e0; e < nnz; e++) {
            int r = __ldg(er + e), c = __ldg(ec + e);
            float v = __ldg(ev + e);
            float4 x = *(const float4*)(g_H0 + (size_t)c * 128 + lane * 4);
            red4(g_F1 + (size_t)r * 128 + lane * 4, v * x.x, v * x.y, v * x.z, v * x.w);
        }
    }
}

__global__ void k_spmm64(const int* __restrict__ er, const int* __restrict__ ec,
                         const float* __restrict__ ev, int nnz)
{
    int idx = blockIdx.x * blockDim.x + threadIdx.x;
    int hw = idx >> 4;
    int l = idx & 15;
    int e0 = hw * 8;
    if (e0 >= nnz) return;
    if (e0 + 8 <= nnz) {
        int4 ra = *(const int4*)(er + e0), rb = *(const int4*)(er + e0 + 4);
        int4 ca = *(const int4*)(ec + e0), cb = *(const int4*)(ec + e0 + 4);
        float4 va = *(const float4*)(ev + e0), vb = *(const float4*)(ev + e0 + 4);
        int rr[8] = {ra.x, ra.y, ra.z, ra.w, rb.x, rb.y, rb.z, rb.w};
        int cc[8] = {ca.x, ca.y, ca.z, ca.w, cb.x, cb.y, cb.z, cb.w};
        float vv[8] = {va.x, va.y, va.z, va.w, vb.x, vb.y, vb.z, vb.w};
        float4 x[8];
#pragma unroll
        for (int i = 0; i < 8; i++)
            x[i] = *(const float4*)(g_H1 + (size_t)cc[i] * 64 + l * 4);
#pragma unroll
        for (int i = 0; i < 8; i++)
            red4(g_F2 + (size_t)rr[i] * 64 + l * 4,
                 vv[i] * x[i].x, vv[i] * x[i].y, vv[i] * x[i].z, vv[i] * x[i].w);
    } else {
        for (int e = e0; e < nnz; e++) {
            int r = __ldg(er + e), c = __ldg(ec + e);
            float v = __ldg(ev + e);
            float4 x = *(const float4*)(g_H1 + (size_t)c * 64 + l * 4);
            red4(g_F2 + (size_t)r * 64 + l * 4, v * x.x, v * x.y, v * x.z, v * x.w);
        }
    }
}

// ============================================================================
// Fused MLP head: layer1 (896->64) bf16x3 mma (R11 config), layers 2/3 FFMA.
// ============================================================================
__global__ __launch_bounds__(256, 2) void k_mlp_mma(
    const int* __restrict__ uIdx, const int* __restrict__ itIdx,
    const float* __restrict__ uE, const float* __restrict__ iE,
    const float* __restrict__ T1b,
    const float* __restrict__ T2W, const float* __restrict__ T2b,
    const float* __restrict__ T3W, const float* __restrict__ T3b,
    float* __restrict__ out, int B)
{
    constexpr int SR = 232;
    constexpr int ABUF = 64 * SR;
    constexpr int OFF_SU = 2 * ABUF * 2;
    constexpr int OFF_SI = OFF_SU + 256;
    constexpr int HSR = 65;
    constexpr int OFF_T2 = 64 * HSR * 4 + 64;
    constexpr int OFF_PART = OFF_T2 + 32 * 64 * 4;
    extern __shared__ __align__(16) char smem[];
    __nv_bfloat16* sA = (__nv_bfloat16*)smem;
    const u32 sbase = smem_u32(smem);
    int* su = (int*)(smem + OFF_SU);
    int* si = (int*)(smem + OFF_SI);

    const int t = threadIdx.x, wid = t >> 5, lane = t & 31;
    const int wm = wid >> 2, wn = wid & 3;
    const int rb = blockIdx.x * 64;

    if (t < 64) {
        int br = rb + t;
        su[t] = (br < B) ? uIdx[br] : 0;
        si[t] = (br < B) ? itIdx[br] : 0;
    }

    float acc[2][2][4];
#pragma unroll
    for (int mt = 0; mt < 2; mt++)
#pragma unroll
        for (int j = 0; j < 2; j++)
#pragma unroll
            for (int q = 0; q < 4; q++) acc[mt][j][q] = 0.f;

    const int arow = lane & 15;
    const int kshift = (lane >> 4) * 8;

    for (int chunk = 0; chunk < 4; chunk++) {
        const int kb = chunk * 224;
        __syncthreads();
#pragma unroll
        for (int it = 0; it < 14; it++) {
            int fid = t + it * 256;
            int r = fid / 56;
            int c4 = (fid % 56) * 4;
            int kg = kb + c4;
            const float* src; int stride, off, rowi;
            if (kg < 256)      { src = uE;   stride = 256; off = kg;       rowi = su[r]; }
            else if (kg < 384) { src = g_F1; stride = 128; off = kg - 256; rowi = su[r]; }
            else if (kg < 448) { src = g_F2; stride = 64;  off = kg - 384; rowi = su[r]; }
            else if (kg < 704) { src = iE;   stride = 256; off = kg - 448; rowi = si[r]; }
            else if (kg < 832) { src = g_F1; stride = 128; off = kg - 704; rowi = si[r] + U_NUM; }
            else               { src = g_F2; stride = 64;  off = kg - 832; rowi = si[r] + U_NUM; }
            float4 v = *(const float4*)(src + (size_t)rowi * stride + off);
            u32 h01, l01, h23, l23;
            split2(v.x, v.y, h01, l01);
            split2(v.z, v.w, h23, l23);
            int so = r * SR + c4;
            *(uint2*)(sA + so)        = make_uint2(h01, h23);
            *(uint2*)(sA + ABUF + so) = make_uint2(l01, l23);
        }
        __syncthreads();

#pragma unroll 2
        for (int ks2 = 0; ks2 < 14; ks2++) {
            const int ks = chunk * 14 + ks2;
            uint4 bw[2];
#pragma unroll
            for (int j = 0; j < 2; j++) {
                int nt = wn * 2 + j;
                bw[j] = __ldg(g_t1f + ((u32)(ks * 8 + nt)) * 32 + lane);
            }
            u32 a[2][2][4];
#pragma unroll
            for (int v = 0; v < 2; v++)
#pragma unroll
                for (int mt = 0; mt < 2; mt++) {
                    int row = wm * 32 + mt * 16 + arow;
                    u32 addr = sbase + (u32)((v * ABUF + row * SR + ks2 * 16 + kshift) * 2);
                    ldm4(a[v][mt], addr);
                }
#pragma unroll
            for (int mt = 0; mt < 2; mt++)
#pragma unroll
                for (int j = 0; j < 2; j++) {
                    mma16816(acc[mt][j], a[0][mt], bw[j].x, bw[j].y);
                    mma16816(acc[mt][j], a[0][mt], bw[j].z, bw[j].w);
                    mma16816(acc[mt][j], a[1][mt], bw[j].x, bw[j].y);
                }
        }
    }
    __syncthreads();

    float* Hs = (float*)smem;
    float* T2s = (float*)(smem + OFF_T2);
    float* part = (float*)(smem + OFF_PART);
    {
        const int rr = wm * 32 + (lane >> 2);
        const int cc = wn * 16 + (lane & 3) * 2;
#pragma unroll
        for (int mt = 0; mt < 2; mt++)
#pragma unroll
            for (int j = 0; j < 2; j++) {
                int c = cc + j * 8;
                float tb0 = __ldg(T1b + c), tb1 = __ldg(T1b + c + 1);
#pragma unroll
                for (int half = 0; half < 2; half++) {
                    int r = rr + mt * 16 + half * 8;
                    Hs[r * HSR + c]     = fmaxf(acc[mt][j][half * 2] + tb0, 0.f);
                    Hs[r * HSR + c + 1] = fmaxf(acc[mt][j][half * 2 + 1] + tb1, 0.f);
                }
            }
    }
#pragma unroll
    for (int i = 0; i < 2; i++) {
        int idx = t + i * 256;
        ((float4*)T2s)[idx] = ((const float4*)T2W)[idx];
    }
    __syncthreads();

    {
        int r = t & 63, g = t >> 6;
        float p = 0.f;
#pragma unroll
        for (int j = 0; j < 8; j++) {
            int c2 = g * 8 + j;
            float s = T2b[c2];
#pragma unroll
            for (int k = 0; k < 64; k++) s += Hs[r * HSR + k] * T2s[c2 * 64 + k];
            p += fmaxf(s, 0.f) * T3W[c2];
        }
        part[g * 64 + r] = p;
    }
    __syncthreads();
    if (t < 64) {
        int br = rb + t;
        if (br < B)
            out[br] = part[t] + part[64 + t] + part[128 + t] + part[192 + t] + T3b[0];
    }
}

// ============================================================================
extern "C" void kernel_launch(void* const* d_in, const int* in_sizes, int n_in,
                              void* d_out, int out_size)
{
    const int*   userIdx = (const int*)d_in[0];
    const int*   itemIdx = (const int*)d_in[1];
    const int*   er      = (const int*)d_in[2];
    const int*   ec      = (const int*)d_in[3];
    const float* ev      = (const float*)d_in[4];
    const float* uE      = (const float*)d_in[5];
    const float* iE      = (const float*)d_in[6];
    const float* W1_0    = (const float*)d_in[7];
    const float* b1_0    = (const float*)d_in[8];
    const float* W2_0    = (const float*)d_in[9];
    const float* b2_0    = (const float*)d_in[10];
    const float* W1_1    = (const float*)d_in[11];
    const float* b1_1    = (const float*)d_in[12];
    const float* W2_1    = (const float*)d_in[13];
    const float* b2_1    = (const float*)d_in[14];
    const float* T1W     = (const float*)d_in[15];
    const float* T1b     = (const float*)d_in[16];
    const float* T2W     = (const float*)d_in[17];
    const float* T2b     = (const float*)d_in[18];
    const float* T3W     = (const float*)d_in[19];
    const float* T3b     = (const float*)d_in[20];
    float* out = (float*)d_out;

    const int B   = in_sizes[0];
    const int nnz = in_sizes[2];

    // gemm0: full-K staging (CHUNK=256), OCC=2
    constexpr int SMEM0 = 2 * 64 * (256 + 8) * 2;    // 67584
    // gemm1: CHUNK=64, OCC=5 (102 regs target)
    constexpr int SMEM1 = 2 * 64 * (64 + 8) * 2;     // 18432
    constexpr int SMEMM = 2 * 64 * 232 * 2 + 1024;   // 60416
    static bool attr_done = false;
    if (!attr_done) {
        cudaFuncSetAttribute((const void*)k_gemm_mma<256, 2, 64, 128, 256, 256, 0, 2, 4>,
                             cudaFuncAttributeMaxDynamicSharedMemorySize, SMEM0);
        cudaFuncSetAttribute((const void*)k_gemm_mma<128, 5, 64, 64, 128, 64, 1, 2, 2>,
                             cudaFuncAttributeMaxDynamicSharedMemorySize, SMEM1);
        cudaFuncSetAttribute((const void*)k_mlp_mma,
                             cudaFuncAttributeMaxDynamicSharedMemorySize, SMEMM);
        attr_done = true;
    }

    k_prep<<<96, 256>>>(W1_0, W2_0, W1_1, W2_1, T1W);

    k_gemm_mma<256, 2, 64, 128, 256, 256, 0, 2, 4>
        <<<(NTOT + 63) / 64, 256, SMEM0>>>(uE, iE, b1_0, b2_0);

    {
        long long warps = ((long long)nnz + 7) / 8;
        int blocks = (int)((warps * 32 + 255) / 256);
        k_spmm128<<<blocks, 256>>>(er, ec, ev, nnz);
    }

    k_gemm_mma<128, 5, 64, 64, 128, 64, 1, 2, 2>
        <<<(NTOT + 63) / 64, 128, SMEM1>>>(uE, iE, b1_1, b2_1);

    {
        long long hws = ((long long)nnz + 7) / 8;
        int blocks = (int)((hws * 16 + 255) / 256);
        k_spmm64<<<blocks, 256>>>(er, ec, ev, nnz);
    }

    k_mlp_mma<<<(B + 63) / 64, 256, SMEMM>>>(userIdx, itemIdx, uE, iE,
                                             T1b, T2W, T2b, T3W, T3b, out, B);
}

// round 14
// speedup vs baseline: 1.0999x; 1.0486x over previous
#include <cuda_runtime.h>
#include <cuda_bf16.h>
#include <cstdint>

#define U_NUM 30000
#define NTOT  100000

typedef unsigned long long u64;
typedef unsigned int u32;

// ---------------- scratch (device globals; allocation-free) ----------------
__device__ __align__(256) float g_H0[(size_t)NTOT * 128];
__device__ __align__(256) float g_F1[(size_t)NTOT * 128];
__device__ __align__(256) float g_H1[(size_t)NTOT * 64];
__device__ __align__(256) float g_F2[(size_t)NTOT * 64];
// fragment-packed bf16 weights: uint4 = {hi01, hi23, lo01, lo23} per [ks][nt][lane]
__device__ __align__(256) uint4 g_w10f[16 * 16 * 32];
__device__ __align__(256) uint4 g_w20f[16 * 16 * 32];
__device__ __align__(256) uint4 g_w11f[8 * 8 * 32];
__device__ __align__(256) uint4 g_w21f[8 * 8 * 32];
__device__ __align__(256) uint4 g_t1f[56 * 8 * 32];

// ---------------- helpers ----------------
__device__ __forceinline__ u32 smem_u32(const void* p) {
    u32 a;
    asm("{ .reg .u64 t; cvta.to.shared.u64 t, %1; cvt.u32.u64 %0, t; }" : "=r"(a) : "l"(p));
    return a;
}
__device__ __forceinline__ void ldm4(u32* r, u32 addr) {
    asm volatile("ldmatrix.sync.aligned.m8n8.x4.shared.b16 {%0,%1,%2,%3}, [%4];"
                 : "=r"(r[0]), "=r"(r[1]), "=r"(r[2]), "=r"(r[3]) : "r"(addr));
}
__device__ __forceinline__ void mma16816(float* c, const u32* a, u32 b0, u32 b1) {
    asm volatile("mma.sync.aligned.m16n8k16.row.col.f32.bf16.bf16.f32 "
                 "{%0,%1,%2,%3}, {%4,%5,%6,%7}, {%8,%9}, {%0,%1,%2,%3};"
                 : "+f"(c[0]), "+f"(c[1]), "+f"(c[2]), "+f"(c[3])
                 : "r"(a[0]), "r"(a[1]), "r"(a[2]), "r"(a[3]), "r"(b0), "r"(b1));
}
__device__ __forceinline__ void split2(float a, float b, u32& hi, u32& lo) {
    __nv_bfloat162 h = __floats2bfloat162_rn(a, b);
    float2 hf = __bfloat1622float2(h);
    __nv_bfloat162 l = __floats2bfloat162_rn(a - hf.x, b - hf.y);
    hi = *reinterpret_cast<u32*>(&h);
    lo = *reinterpret_cast<u32*>(&l);
}
__device__ __forceinline__ u32 sq_bf16x2(u32 x) {
    __nv_bfloat162 h = *reinterpret_cast<__nv_bfloat162*>(&x);
    __nv_bfloat162 s = __hmul2(h, h);
    return *reinterpret_cast<u32*>(&s);
}
__device__ __forceinline__ void red4(float* p, float a, float b, float c, float d) {
    asm volatile("{ .reg .u64 q; cvta.to.global.u64 q, %0; red.global.add.v4.f32 [q], {%1,%2,%3,%4}; }"
                 :: "l"(p), "f"(a), "f"(b), "f"(c), "f"(d) : "memory");
}
__device__ __forceinline__ void cpasync16(u32 dst, const void* src, bool valid) {
    int sz = valid ? 16 : 0;
    asm volatile("cp.async.cg.shared.global [%0], [%1], 16, %2;"
                 :: "r"(dst), "l"(src), "r"(sz) : "memory");
}

// ============================================================================
// Weight fragment prep
// ============================================================================
__device__ __forceinline__ void pack_frag(const float* __restrict__ W, uint4* __restrict__ dst,
                                          int ks, int nt, int lane, int NT, int K)
{
    int n = nt * 8 + (lane >> 2);
    int k = ks * 16 + (lane & 3) * 2;
    const float* p = W + (size_t)n * K + k;
    float x0 = p[0], x1 = p[1], x2 = p[8], x3 = p[9];
    u32 h01, l01, h23, l23;
    split2(x0, x1, h01, l01);
    split2(x2, x3, h23, l23);
    dst[((size_t)ks * NT + nt) * 32 + lane] = make_uint4(h01, h23, l01, l23);
}

__global__ void k_prep(const float* __restrict__ W10, const float* __restrict__ W20,
                       const float* __restrict__ W11, const float* __restrict__ W21,
                       const float* __restrict__ T1W)
{
    int i = blockIdx.x * 256 + threadIdx.x;
    if (i < 8192) {
        int lane = i & 31, nt = (i >> 5) & 15, ks = i >> 9;
        pack_frag(W10, g_w10f, ks, nt, lane, 16, 256);
        pack_frag(W20, g_w20f, ks, nt, lane, 16, 256);
    } else if (i < 10240) {
        int j = i - 8192;
        int lane = j & 31, nt = (j >> 5) & 7, ks = j >> 8;
        pack_frag(W11, g_w11f, ks, nt, lane, 8, 128);
        pack_frag(W21, g_w21f, ks, nt, lane, 8, 128);
    } else if (i < 24576) {
        int j = i - 10240;
        int lane = j & 31, nt = (j >> 5) & 7, ks = j >> 8;
        pack_frag(T1W, g_t1f, ks, nt, lane, 8, 896);
    }
}

// ============================================================================
// Fused dual GEMM with cp.async double-buffered raw staging (NCH must be <=2).
// Main path bf16x3 compensated; square-path A fragment derived in registers.
//   Fout = A@W1^T + (b1+b2),  Hout = A@W1^T + (A*A)@W2^T
// ============================================================================
template<int THREADS, int OCC, int BM, int DOUT, int KTOT, int CHUNK,
         int MODE, int WM_N, int WN_N>
__global__ __launch_bounds__(THREADS, OCC) void k_gemm_mma(
    const float* __restrict__ uE, const float* __restrict__ iE,
    const float* __restrict__ b1, const float* __restrict__ b2)
{
    constexpr int SR = CHUNK + 8;
    constexpr int ABUF = BM * SR;          // bf16 elems per variant
    constexpr int RAWR = CHUNK + 4;        // fp32 raw row stride
    constexpr int RAWBUF = BM * RAWR;      // fp32 elems per raw buffer
    constexpr int NCH = KTOT / CHUNK;
    static_assert(NCH <= 2, "pipeline assumes <=2 chunks");
    constexpr int KS_C = CHUNK / 16;
    constexpr int NT = DOUT / 8;
    constexpr int JW = NT / WN_N;
    constexpr int F4R = CHUNK / 4;
    constexpr int RAW_OFF = 2 * ABUF * 2;  // bytes
    extern __shared__ __align__(16) char smem[];
    __nv_bfloat16* sA = (__nv_bfloat16*)smem;
    float* sRaw = (float*)(smem + RAW_OFF);
    const u32 sbase = smem_u32(smem);
    const u32 rawbase = sbase + RAW_OFF;

    const uint4* __restrict__ w1f = (MODE == 0) ? g_w10f : g_w11f;
    const uint2* __restrict__ w2f = (MODE == 0) ? (const uint2*)g_w20f : (const uint2*)g_w21f;
    float* __restrict__ Fout = (MODE == 0) ? g_F1 : g_F2;
    float* __restrict__ Hout = (MODE == 0) ? g_H0 : g_H1;

    const int t = threadIdx.x, wid = t >> 5, lane = t & 31;
    const int wm = wid / WN_N, wn = wid % WN_N;
    const int row0 = blockIdx.x * BM;

    // ---- issue async loads of ALL chunks up-front ----
#pragma unroll
    for (int ch = 0; ch < NCH; ch++) {
#pragma unroll
        for (int it = 0; it < BM * F4R / THREADS; it++) {
            int fid = t + it * THREADS;
            int r = fid / F4R;
            int c4 = (fid % F4R) * 4;
            int gr = row0 + r;
            bool valid = gr < NTOT;
            int grs = valid ? gr : 0;
            const float* gp;
            if (MODE == 0) gp = (grs < U_NUM) ? uE + (size_t)grs * 256 + ch * CHUNK + c4
                                              : iE + (size_t)(grs - U_NUM) * 256 + ch * CHUNK + c4;
            else           gp = g_F1 + (size_t)grs * 128 + ch * CHUNK + c4;
            u32 dst = rawbase + (u32)((ch * RAWBUF + r * RAWR + c4) * 4);
            cpasync16(dst, gp, valid);
        }
        asm volatile("cp.async.commit_group;" ::: "memory");
    }

    float acc1[2][JW][4], acc2[2][JW][4];
#pragma unroll
    for (int mt = 0; mt < 2; mt++)
#pragma unroll
        for (int j = 0; j < JW; j++)
#pragma unroll
            for (int q = 0; q < 4; q++) { acc1[mt][j][q] = 0.f; acc2[mt][j][q] = 0.f; }

    const int arow = lane & 15;
    const int kshift = (lane >> 4) * 8;

#pragma unroll
    for (int ch = 0; ch < NCH; ch++) {
        if (ch == 0 && NCH > 1)
            asm volatile("cp.async.wait_group 1;" ::: "memory");
        else
            asm volatile("cp.async.wait_group 0;" ::: "memory");
        __syncthreads();
        // ---- convert raw fp32 -> {hi, lo} bf16 (pure SMEM traffic) ----
#pragma unroll
        for (int it = 0; it < BM * F4R / THREADS; it++) {
            int fid = t + it * THREADS;
            int r = fid / F4R;
            int c4 = (fid % F4R) * 4;
            float4 v = *(const float4*)(sRaw + ch * RAWBUF + r * RAWR + c4);
            u32 h01, l01, h23, l23;
            split2(v.x, v.y, h01, l01);
            split2(v.z, v.w, h23, l23);
            int off = r * SR + c4;
            *(uint2*)(sA + off)        = make_uint2(h01, h23);
            *(uint2*)(sA + ABUF + off) = make_uint2(l01, l23);
        }
        __syncthreads();

#pragma unroll 2
        for (int ks2 = 0; ks2 < KS_C; ks2++) {
            const int ks = ch * KS_C + ks2;
            u32 a[2][2][4];
#pragma unroll
            for (int v = 0; v < 2; v++)
#pragma unroll
                for (int mt = 0; mt < 2; mt++) {
                    int row = wm * 32 + mt * 16 + arow;
                    u32 addr = sbase + (u32)((v * ABUF + row * SR + ks2 * 16 + kshift) * 2);
                    ldm4(a[v][mt], addr);
                }
            u32 asq[2][4];
#pragma unroll
            for (int mt = 0; mt < 2; mt++)
#pragma unroll
                for (int i = 0; i < 4; i++)
                    asq[mt][i] = sq_bf16x2(a[0][mt][i]);

#pragma unroll
            for (int h = 0; h < (JW + 1) / 2; h++) {
                constexpr int JH = (JW >= 2) ? 2 : 1;
                uint4 bw1[JH];
                uint2 bw2[JH];
#pragma unroll
                for (int jj = 0; jj < JH; jj++) {
                    int nt = wn * JW + h * JH + jj;
                    u32 idx = ((u32)(ks * NT + nt)) * 32 + lane;
                    bw1[jj] = __ldg(w1f + idx);
                    bw2[jj] = __ldg(w2f + (size_t)idx * 2);
                }
#pragma unroll
                for (int mt = 0; mt < 2; mt++)
#pragma unroll
                    for (int jj = 0; jj < JH; jj++) {
                        int j = h * JH + jj;
                        mma16816(acc1[mt][j], a[0][mt], bw1[jj].x, bw1[jj].y);
                        mma16816(acc1[mt][j], a[0][mt], bw1[jj].z, bw1[jj].w);
                        mma16816(acc1[mt][j], a[1][mt], bw1[jj].x, bw1[jj].y);
                        mma16816(acc2[mt][j], asq[mt],  bw2[jj].x, bw2[jj].y);
                    }
            }
        }
    }

    // ---- epilogue ----
    const int r_base = row0 + wm * 32 + (lane >> 2);
    const int c_base = wn * (JW * 8) + (lane & 3) * 2;
#pragma unroll
    for (int mt = 0; mt < 2; mt++)
#pragma unroll
        for (int j = 0; j < JW; j++) {
            int c = c_base + j * 8;
            float bs0 = __ldg(b1 + c) + __ldg(b2 + c);
            float bs1 = __ldg(b1 + c + 1) + __ldg(b2 + c + 1);
#pragma unroll
            for (int half = 0; half < 2; half++) {
                int r = r_base + mt * 16 + half * 8;
                if (r < NTOT) {
                    float a0 = acc1[mt][j][half * 2], a1 = acc1[mt][j][half * 2 + 1];
                    float2 f = make_float2(a0 + bs0, a1 + bs1);
                    float2 h2 = make_float2(a0 + acc2[mt][j][half * 2],
                                            a1 + acc2[mt][j][half * 2 + 1]);
                    *(float2*)(Fout + (size_t)r * DOUT + c) = f;
                    *(float2*)(Hout + (size_t)r * DOUT + c) = h2;
                }
            }
        }
}

// ============================================================================
// SpMM scatter: F[row] += val * H[col].  8 edges per (sub)warp.
// ============================================================================
__global__ void k_spmm128(const int* __restrict__ er, const int* __restrict__ ec,
                          const float* __restrict__ ev, int nnz)
{
    int w = (blockIdx.x * blockDim.x + threadIdx.x) >> 5;
    int lane = threadIdx.x & 31;
    int e0 = w * 8;
    if (e0 >= nnz) return;
    if (e0 + 8 <= nnz) {
        int4 ra = *(const int4*)(er + e0), rb = *(const int4*)(er + e0 + 4);
        int4 ca = *(const int4*)(ec + e0), cb = *(const int4*)(ec + e0 + 4);
        float4 va = *(const float4*)(ev + e0), vb = *(const float4*)(ev + e0 + 4);
        int rr[8] = {ra.x, ra.y, ra.z, ra.w, rb.x, rb.y, rb.z, rb.w};
        int cc[8] = {ca.x, ca.y, ca.z, ca.w, cb.x, cb.y, cb.z, cb.w};
        float vv[8] = {va.x, va.y, va.z, va.w, vb.x, vb.y, vb.z, vb.w};
        float4 x[8];
#pragma unroll
        for (int i = 0; i < 8; i++)
            x[i] = *(const float4*)(g_H0 + (size_t)cc[i] * 128 + lane * 4);
#pragma unroll
        for (int i = 0; i < 8; i++)
            red4(g_F1 + (size_t)rr[i] * 128 + lane * 4,
                 vv[i] * x[i].x, vv[i] * x[i].y, vv[i] * x[i].z, vv[i] * x[i].w);
    } else {
        for (int e = e0; e < nnz; e++) {
            int r = __ldg(er + e), c = __ldg(ec + e);
            float v = __ldg(ev + e);
            float4 x = *(const float4*)(g_H0 + (size_t)c * 128 + lane * 4);
            red4(g_F1 + (size_t)r * 128 + lane * 4, v * x.x, v * x.y, v * x.z, v * x.w);
        }
    }
}

__global__ void k_spmm64(const int* __restrict__ er, const int* __restrict__ ec,
                         const float* __restrict__ ev, int nnz)
{
    int idx = blockIdx.x * blockDim.x + threadIdx.x;
    int hw = idx >> 4;
    int l = idx & 15;
    int e0 = hw * 8;
    if (e0 >= nnz) return;
    if (e0 + 8 <= nnz) {
        int4 ra = *(const int4*)(er + e0), rb = *(const int4*)(er + e0 + 4);
        int4 ca = *(const int4*)(ec + e0), cb = *(const int4*)(ec + e0 + 4);
        float4 va = *(const float4*)(ev + e0), vb = *(const float4*)(ev + e0 + 4);
        int rr[8] = {ra.x, ra.y, ra.z, ra.w, rb.x, rb.y, rb.z, rb.w};
        int cc[8] = {ca.x, ca.y, ca.z, ca.w, cb.x, cb.y, cb.z, cb.w};
        float vv[8] = {va.x, va.y, va.z, va.w, vb.x, vb.y, vb.z, vb.w};
        float4 x[8];
#pragma unroll
        for (int i = 0; i < 8; i++)
            x[i] = *(const float4*)(g_H1 + (size_t)cc[i] * 64 + l * 4);
#pragma unroll
        for (int i = 0; i < 8; i++)
            red4(g_F2 + (size_t)rr[i] * 64 + l * 4,
                 vv[i] * x[i].x, vv[i] * x[i].y, vv[i] * x[i].z, vv[i] * x[i].w);
    } else {
        for (int e = e0; e < nnz; e++) {
            int r = __ldg(er + e), c = __ldg(ec + e);
            float v = __ldg(ev + e);
            float4 x = *(const float4*)(g_H1 + (size_t)c * 64 + l * 4);
            red4(g_F2 + (size_t)r * 64 + l * 4, v * x.x, v * x.y, v * x.z, v * x.w);
        }
    }
}

// ============================================================================
// Fused MLP head: layer1 (896->64) bf16x3 mma (R11 config), layers 2/3 FFMA.
// ============================================================================
__global__ __launch_bounds__(256, 2) void k_mlp_mma(
    const int* __restrict__ uIdx, const int* __restrict__ itIdx,
    const float* __restrict__ uE, const float* __restrict__ iE,
    const float* __restrict__ T1b,
    const float* __restrict__ T2W, const float* __restrict__ T2b,
    const float* __restrict__ T3W, const float* __restrict__ T3b,
    float* __restrict__ out, int B)
{
    constexpr int SR = 232;
    constexpr int ABUF = 64 * SR;
    constexpr int OFF_SU = 2 * ABUF * 2;
    constexpr int OFF_SI = OFF_SU + 256;
    constexpr int HSR = 65;
    constexpr int OFF_T2 = 64 * HSR * 4 + 64;
    constexpr int OFF_PART = OFF_T2 + 32 * 64 * 4;
    extern __shared__ __align__(16) char smem[];
    __nv_bfloat16* sA = (__nv_bfloat16*)smem;
    const u32 sbase = smem_u32(smem);
    int* su = (int*)(smem + OFF_SU);
    int* si = (int*)(smem + OFF_SI);

    const int t = threadIdx.x, wid = t >> 5, lane = t & 31;
    const int wm = wid >> 2, wn = wid & 3;
    const int rb = blockIdx.x * 64;

    if (t < 64) {
        int br = rb + t;
        su[t] = (br < B) ? uIdx[br] : 0;
        si[t] = (br < B) ? itIdx[br] : 0;
    }

    float acc[2][2][4];
#pragma unroll
    for (int mt = 0; mt < 2; mt++)
#pragma unroll
        for (int j = 0; j < 2; j++)
#pragma unroll
            for (int q = 0; q < 4; q++) acc[mt][j][q] = 0.f;

    const int arow = lane & 15;
    const int kshift = (lane >> 4) * 8;

    for (int chunk = 0; chunk < 4; chunk++) {
        const int kb = chunk * 224;
        __syncthreads();
#pragma unroll
        for (int it = 0; it < 14; it++) {
            int fid = t + it * 256;
            int r = fid / 56;
            int c4 = (fid % 56) * 4;
            int kg = kb + c4;
            const float* src; int stride, off, rowi;
            if (kg < 256)      { src = uE;   stride = 256; off = kg;       rowi = su[r]; }
            else if (kg < 384) { src = g_F1; stride = 128; off = kg - 256; rowi = su[r]; }
            else if (kg < 448) { src = g_F2; stride = 64;  off = kg - 384; rowi = su[r]; }
            else if (kg < 704) { src = iE;   stride = 256; off = kg - 448; rowi = si[r]; }
            else if (kg < 832) { src = g_F1; stride = 128; off = kg - 704; rowi = si[r] + U_NUM; }
            else               { src = g_F2; stride = 64;  off = kg - 832; rowi = si[r] + U_NUM; }
            float4 v = *(const float4*)(src + (size_t)rowi * stride + off);
            u32 h01, l01, h23, l23;
            split2(v.x, v.y, h01, l01);
            split2(v.z, v.w, h23, l23);
            int so = r * SR + c4;
            *(uint2*)(sA + so)        = make_uint2(h01, h23);
            *(uint2*)(sA + ABUF + so) = make_uint2(l01, l23);
        }
        __syncthreads();

#pragma unroll 2
        for (int ks2 = 0; ks2 < 14; ks2++) {
            const int ks = chunk * 14 + ks2;
            uint4 bw[2];
#pragma unroll
            for (int j = 0; j < 2; j++) {
                int nt = wn * 2 + j;
                bw[j] = __ldg(g_t1f + ((u32)(ks * 8 + nt)) * 32 + lane);
            }
            u32 a[2][2][4];
#pragma unroll
            for (int v = 0; v < 2; v++)
#pragma unroll
                for (int mt = 0; mt < 2; mt++) {
                    int row = wm * 32 + mt * 16 + arow;
                    u32 addr = sbase + (u32)((v * ABUF + row * SR + ks2 * 16 + kshift) * 2);
                    ldm4(a[v][mt], addr);
                }
#pragma unroll
            for (int mt = 0; mt < 2; mt++)
#pragma unroll
                for (int j = 0; j < 2; j++) {
                    mma16816(acc[mt][j], a[0][mt], bw[j].x, bw[j].y);
                    mma16816(acc[mt][j], a[0][mt], bw[j].z, bw[j].w);
                    mma16816(acc[mt][j], a[1][mt], bw[j].x, bw[j].y);
                }
        }
    }
    __syncthreads();

    float* Hs = (float*)smem;
    float* T2s = (float*)(smem + OFF_T2);
    float* part = (float*)(smem + OFF_PART);
    {
        const int rr = wm * 32 + (lane >> 2);
        const int cc = wn * 16 + (lane & 3) * 2;
#pragma unroll
        for (int mt = 0; mt < 2; mt++)
#pragma unroll
            for (int j = 0; j < 2; j++) {
                int c = cc + j * 8;
                float tb0 = __ldg(T1b + c), tb1 = __ldg(T1b + c + 1);
#pragma unroll
                for (int half = 0; half < 2; half++) {
                    int r = rr + mt * 16 + half * 8;
                    Hs[r * HSR + c]     = fmaxf(acc[mt][j][half * 2] + tb0, 0.f);
                    Hs[r * HSR + c + 1] = fmaxf(acc[mt][j][half * 2 + 1] + tb1, 0.f);
                }
            }
    }
#pragma unroll
    for (int i = 0; i < 2; i++) {
        int idx = t + i * 256;
        ((float4*)T2s)[idx] = ((const float4*)T2W)[idx];
    }
    __syncthreads();

    {
        int r = t & 63, g = t >> 6;
        float p = 0.f;
#pragma unroll
        for (int j = 0; j < 8; j++) {
            int c2 = g * 8 + j;
            float s = T2b[c2];
#pragma unroll
            for (int k = 0; k < 64; k++) s += Hs[r * HSR + k] * T2s[c2 * 64 + k];
            p += fmaxf(s, 0.f) * T3W[c2];
        }
        part[g * 64 + r] = p;
    }
    __syncthreads();
    if (t < 64) {
        int br = rb + t;
        if (br < B)
            out[br] = part[t] + part[64 + t] + part[128 + t] + part[192 + t] + T3b[0];
    }
}

// ============================================================================
extern "C" void kernel_launch(void* const* d_in, const int* in_sizes, int n_in,
                              void* d_out, int out_size)
{
    const int*   userIdx = (const int*)d_in[0];
    const int*   itemIdx = (const int*)d_in[1];
    const int*   er      = (const int*)d_in[2];
    const int*   ec      = (const int*)d_in[3];
    const float* ev      = (const float*)d_in[4];
    const float* uE      = (const float*)d_in[5];
    const float* iE      = (const float*)d_in[6];
    const float* W1_0    = (const float*)d_in[7];
    const float* b1_0    = (const float*)d_in[8];
    const float* W2_0    = (const float*)d_in[9];
    const float* b2_0    = (const float*)d_in[10];
    const float* W1_1    = (const float*)d_in[11];
    const float* b1_1    = (const float*)d_in[12];
    const float* W2_1    = (const float*)d_in[13];
    const float* b2_1    = (const float*)d_in[14];
    const float* T1W     = (const float*)d_in[15];
    const float* T1b     = (const float*)d_in[16];
    const float* T2W     = (const float*)d_in[17];
    const float* T2b     = (const float*)d_in[18];
    const float* T3W     = (const float*)d_in[19];
    const float* T3b     = (const float*)d_in[20];
    float* out = (float*)d_out;

    const int B   = in_sizes[0];
    const int nnz = in_sizes[2];

    // gemm0: bf16 bufs 34816 + raw 2*64*132*4 = 67584 -> 102400, OCC=2
    constexpr int SMEM0 = 2 * 64 * (128 + 8) * 2 + 2 * 64 * (128 + 4) * 4;
    // gemm1: bf16 bufs 18432 + raw 2*64*68*4 = 34816 -> 53248, OCC=4
    constexpr int SMEM1 = 2 * 64 * (64 + 8) * 2 + 2 * 64 * (64 + 4) * 4;
    constexpr int SMEMM = 2 * 64 * 232 * 2 + 1024;   // 60416
    static bool attr_done = false;
    if (!attr_done) {
        cudaFuncSetAttribute((const void*)k_gemm_mma<256, 2, 64, 128, 256, 128, 0, 2, 4>,
                             cudaFuncAttributeMaxDynamicSharedMemorySize, SMEM0);
        cudaFuncSetAttribute((const void*)k_gemm_mma<128, 4, 64, 64, 128, 64, 1, 2, 2>,
                             cudaFuncAttributeMaxDynamicSharedMemorySize, SMEM1);
        cudaFuncSetAttribute((const void*)k_mlp_mma,
                             cudaFuncAttributeMaxDynamicSharedMemorySize, SMEMM);
        attr_done = true;
    }

    k_prep<<<96, 256>>>(W1_0, W2_0, W1_1, W2_1, T1W);

    k_gemm_mma<256, 2, 64, 128, 256, 128, 0, 2, 4>
        <<<(NTOT + 63) / 64, 256, SMEM0>>>(uE, iE, b1_0, b2_0);

    {
        long long warps = ((long long)nnz + 7) / 8;
        int blocks = (int)((warps * 32 + 255) / 256);
        k_spmm128<<<blocks, 256>>>(er, ec, ev, nnz);
    }

    k_gemm_mma<128, 4, 64, 64, 128, 64, 1, 2, 2>
        <<<(NTOT + 63) / 64, 128, SMEM1>>>(uE, iE, b1_1, b2_1);

    {
        long long hws = ((long long)nnz + 7) / 8;
        int blocks = (int)((hws * 16 + 255) / 256);
        k_spmm64<<<blocks, 256>>>(er, ec, ev, nnz);
    }

    k_mlp_mma<<<(B + 63) / 64, 256, SMEMM>>>(userIdx, itemIdx, uE, iE,
                                             T1b, T2W, T2b, T3W, T3b, out, B);
}

// round 15
// speedup vs baseline: 1.1026x; 1.0025x over previous
#include <cuda_runtime.h>
#include <cuda_bf16.h>
#include <cstdint>

#define U_NUM 30000
#define NTOT  100000

typedef unsigned long long u64;
typedef unsigned int u32;

// ---------------- scratch (device globals; allocation-free) ----------------
__device__ __align__(256) float g_H0[(size_t)NTOT * 128];
__device__ __align__(256) float g_F1[(size_t)NTOT * 128];
__device__ __align__(256) float g_H1[(size_t)NTOT * 64];
__device__ __align__(256) float g_F2[(size_t)NTOT * 64];
// fragment-packed bf16 weights: uint4 = {hi01, hi23, lo01, lo23} per [ks][nt][lane]
__device__ __align__(256) uint4 g_w10f[16 * 16 * 32];
__device__ __align__(256) uint4 g_w20f[16 * 16 * 32];
__device__ __align__(256) uint4 g_w11f[8 * 8 * 32];
__device__ __align__(256) uint4 g_w21f[8 * 8 * 32];
__device__ __align__(256) uint4 g_t1f[56 * 8 * 32];

// ---------------- helpers ----------------
__device__ __forceinline__ u32 smem_u32(const void* p) {
    u32 a;
    asm("{ .reg .u64 t; cvta.to.shared.u64 t, %1; cvt.u32.u64 %0, t; }" : "=r"(a) : "l"(p));
    return a;
}
__device__ __forceinline__ void ldm4(u32* r, u32 addr) {
    asm volatile("ldmatrix.sync.aligned.m8n8.x4.shared.b16 {%0,%1,%2,%3}, [%4];"
                 : "=r"(r[0]), "=r"(r[1]), "=r"(r[2]), "=r"(r[3]) : "r"(addr));
}
__device__ __forceinline__ void mma16816(float* c, const u32* a, u32 b0, u32 b1) {
    asm volatile("mma.sync.aligned.m16n8k16.row.col.f32.bf16.bf16.f32 "
                 "{%0,%1,%2,%3}, {%4,%5,%6,%7}, {%8,%9}, {%0,%1,%2,%3};"
                 : "+f"(c[0]), "+f"(c[1]), "+f"(c[2]), "+f"(c[3])
                 : "r"(a[0]), "r"(a[1]), "r"(a[2]), "r"(a[3]), "r"(b0), "r"(b1));
}
__device__ __forceinline__ void split2(float a, float b, u32& hi, u32& lo) {
    __nv_bfloat162 h = __floats2bfloat162_rn(a, b);
    float2 hf = __bfloat1622float2(h);
    __nv_bfloat162 l = __floats2bfloat162_rn(a - hf.x, b - hf.y);
    hi = *reinterpret_cast<u32*>(&h);
    lo = *reinterpret_cast<u32*>(&l);
}
__device__ __forceinline__ u32 sq_bf16x2(u32 x) {
    __nv_bfloat162 h = *reinterpret_cast<__nv_bfloat162*>(&x);
    __nv_bfloat162 s = __hmul2(h, h);
    return *reinterpret_cast<u32*>(&s);
}
__device__ __forceinline__ void red4(float* p, float a, float b, float c, float d) {
    asm volatile("{ .reg .u64 q; cvta.to.global.u64 q, %0; red.global.add.v4.f32 [q], {%1,%2,%3,%4}; }"
                 :: "l"(p), "f"(a), "f"(b), "f"(c), "f"(d) : "memory");
}

// ============================================================================
// Weight fragment prep (split into 3 kernels so gemm0 lands at ncu launch idx 3)
// ============================================================================
__device__ __forceinline__ void pack_frag(const float* __restrict__ W, uint4* __restrict__ dst,
                                          int ks, int nt, int lane, int NT, int K)
{
    int n = nt * 8 + (lane >> 2);
    int k = ks * 16 + (lane & 3) * 2;
    const float* p = W + (size_t)n * K + k;
    float x0 = p[0], x1 = p[1], x2 = p[8], x3 = p[9];
    u32 h01, l01, h23, l23;
    split2(x0, x1, h01, l01);
    split2(x2, x3, h23, l23);
    dst[((size_t)ks * NT + nt) * 32 + lane] = make_uint4(h01, h23, l01, l23);
}

__global__ void k_prep0(const float* __restrict__ W10, const float* __restrict__ W20)
{
    int i = blockIdx.x * 256 + threadIdx.x;
    if (i < 8192) {
        int lane = i & 31, nt = (i >> 5) & 15, ks = i >> 9;
        pack_frag(W10, g_w10f, ks, nt, lane, 16, 256);
        pack_frag(W20, g_w20f, ks, nt, lane, 16, 256);
    }
}
__global__ void k_prep1(const float* __restrict__ W11, const float* __restrict__ W21)
{
    int i = blockIdx.x * 256 + threadIdx.x;
    if (i < 2048) {
        int lane = i & 31, nt = (i >> 5) & 7, ks = i >> 8;
        pack_frag(W11, g_w11f, ks, nt, lane, 8, 128);
        pack_frag(W21, g_w21f, ks, nt, lane, 8, 128);
    }
}
__global__ void k_prep2(const float* __restrict__ T1W)
{
    int i = blockIdx.x * 256 + threadIdx.x;
    if (i < 14336) {
        int lane = i & 31, nt = (i >> 5) & 7, ks = i >> 8;
        pack_frag(T1W, g_t1f, ks, nt, lane, 8, 896);
    }
}

// ============================================================================
// Fused dual GEMM (R11 config): main path bf16x3 compensated; square path's A
// fragment derived in registers (HMUL2 of the hi fragment).
//   Fout = A@W1^T + (b1+b2),  Hout = A@W1^T + (A*A)@W2^T
// ============================================================================
template<int THREADS, int OCC, int BM, int DOUT, int KTOT, int CHUNK,
         int MODE, int WM_N, int WN_N>
__global__ __launch_bounds__(THREADS, OCC) void k_gemm_mma(
    const float* __restrict__ uE, const float* __restrict__ iE,
    const float* __restrict__ b1, const float* __restrict__ b2)
{
    constexpr int SR = CHUNK + 8;
    constexpr int ABUF = BM * SR;
    constexpr int NCH = KTOT / CHUNK;
    constexpr int KS_C = CHUNK / 16;
    constexpr int NT = DOUT / 8;
    constexpr int JW = NT / WN_N;
    constexpr int F4R = CHUNK / 4;
    extern __shared__ __align__(16) char smem[];
    __nv_bfloat16* sA = (__nv_bfloat16*)smem;
    const u32 sbase = smem_u32(smem);

    const uint4* __restrict__ w1f = (MODE == 0) ? g_w10f : g_w11f;
    const uint2* __restrict__ w2f = (MODE == 0) ? (const uint2*)g_w20f : (const uint2*)g_w21f;
    float* __restrict__ Fout = (MODE == 0) ? g_F1 : g_F2;
    float* __restrict__ Hout = (MODE == 0) ? g_H0 : g_H1;

    const int t = threadIdx.x, wid = t >> 5, lane = t & 31;
    const int wm = wid / WN_N, wn = wid % WN_N;
    const int row0 = blockIdx.x * BM;

    float acc1[2][JW][4], acc2[2][JW][4];
#pragma unroll
    for (int mt = 0; mt < 2; mt++)
#pragma unroll
        for (int j = 0; j < JW; j++)
#pragma unroll
            for (int q = 0; q < 4; q++) { acc1[mt][j][q] = 0.f; acc2[mt][j][q] = 0.f; }

    const int arow = lane & 15;
    const int kshift = (lane >> 4) * 8;

    for (int ch = 0; ch < NCH; ch++) {
        __syncthreads();
#pragma unroll
        for (int it = 0; it < BM * F4R / THREADS; it++) {
            int fid = t + it * THREADS;
            int r = fid / F4R;
            int c4 = (fid % F4R) * 4;
            int gr = row0 + r;
            float4 v = make_float4(0.f, 0.f, 0.f, 0.f);
            if (gr < NTOT) {
                const float* src;
                if (MODE == 0) src = (gr < U_NUM) ? uE + (size_t)gr * 256
                                                  : iE + (size_t)(gr - U_NUM) * 256;
                else           src = g_F1 + (size_t)gr * 128;
                v = *(const float4*)(src + ch * CHUNK + c4);
            }
            u32 h01, l01, h23, l23;
            split2(v.x, v.y, h01, l01);
            split2(v.z, v.w, h23, l23);
            int off = r * SR + c4;
            *(uint2*)(sA + off)        = make_uint2(h01, h23);
            *(uint2*)(sA + ABUF + off) = make_uint2(l01, l23);
        }
        __syncthreads();

#pragma unroll 2
        for (int ks2 = 0; ks2 < KS_C; ks2++) {
            const int ks = ch * KS_C + ks2;
            u32 a[2][2][4];
#pragma unroll
            for (int v = 0; v < 2; v++)
#pragma unroll
                for (int mt = 0; mt < 2; mt++) {
                    int row = wm * 32 + mt * 16 + arow;
                    u32 addr = sbase + (u32)((v * ABUF + row * SR + ks2 * 16 + kshift) * 2);
                    ldm4(a[v][mt], addr);
                }
            u32 asq[2][4];
#pragma unroll
            for (int mt = 0; mt < 2; mt++)
#pragma unroll
                for (int i = 0; i < 4; i++)
                    asq[mt][i] = sq_bf16x2(a[0][mt][i]);

#pragma unroll
            for (int h = 0; h < (JW + 1) / 2; h++) {
                constexpr int JH = (JW >= 2) ? 2 : 1;
                uint4 bw1[JH];
                uint2 bw2[JH];
#pragma unroll
                for (int jj = 0; jj < JH; jj++) {
                    int nt = wn * JW + h * JH + jj;
                    u32 idx = ((u32)(ks * NT + nt)) * 32 + lane;
                    bw1[jj] = __ldg(w1f + idx);
                    bw2[jj] = __ldg(w2f + (size_t)idx * 2);
                }
#pragma unroll
                for (int mt = 0; mt < 2; mt++)
#pragma unroll
                    for (int jj = 0; jj < JH; jj++) {
                        int j = h * JH + jj;
                        mma16816(acc1[mt][j], a[0][mt], bw1[jj].x, bw1[jj].y);
                        mma16816(acc1[mt][j], a[0][mt], bw1[jj].z, bw1[jj].w);
                        mma16816(acc1[mt][j], a[1][mt], bw1[jj].x, bw1[jj].y);
                        mma16816(acc2[mt][j], asq[mt],  bw2[jj].x, bw2[jj].y);
                    }
            }
        }
    }

    const int r_base = row0 + wm * 32 + (lane >> 2);
    const int c_base = wn * (JW * 8) + (lane & 3) * 2;
#pragma unroll
    for (int mt = 0; mt < 2; mt++)
#pragma unroll
        for (int j = 0; j < JW; j++) {
            int c = c_base + j * 8;
            float bs0 = __ldg(b1 + c) + __ldg(b2 + c);
            float bs1 = __ldg(b1 + c + 1) + __ldg(b2 + c + 1);
#pragma unroll
            for (int half = 0; half < 2; half++) {
                int r = r_base + mt * 16 + half * 8;
                if (r < NTOT) {
                    float a0 = acc1[mt][j][half * 2], a1 = acc1[mt][j][half * 2 + 1];
                    float2 f = make_float2(a0 + bs0, a1 + bs1);
                    float2 h2 = make_float2(a0 + acc2[mt][j][half * 2],
                                            a1 + acc2[mt][j][half * 2 + 1]);
                    *(float2*)(Fout + (size_t)r * DOUT + c) = f;
                    *(float2*)(Hout + (size_t)r * DOUT + c) = h2;
                }
            }
        }
}

// ============================================================================
// SpMM scatter: F[row] += val * H[col].  8 edges per (sub)warp.
// ============================================================================
__global__ void k_spmm128(const int* __restrict__ er, const int* __restrict__ ec,
                          const float* __restrict__ ev, int nnz)
{
    int w = (blockIdx.x * blockDim.x + threadIdx.x) >> 5;
    int lane = threadIdx.x & 31;
    int e0 = w * 8;
    if (e0 >= nnz) return;
    if (e0 + 8 <= nnz) {
        int4 ra = *(const int4*)(er + e0), rb = *(const int4*)(er + e0 + 4);
        int4 ca = *(const int4*)(ec + e0), cb = *(const int4*)(ec + e0 + 4);
        float4 va = *(const float4*)(ev + e0), vb = *(const float4*)(ev + e0 + 4);
        int rr[8] = {ra.x, ra.y, ra.z, ra.w, rb.x, rb.y, rb.z, rb.w};
        int cc[8] = {ca.x, ca.y, ca.z, ca.w, cb.x, cb.y, cb.z, cb.w};
        float vv[8] = {va.x, va.y, va.z, va.w, vb.x, vb.y, vb.z, vb.w};
        float4 x[8];
#pragma unroll
        for (int i = 0; i < 8; i++)
            x[i] = *(const float4*)(g_H0 + (size_t)cc[i] * 128 + lane * 4);
#pragma unroll
        for (int i = 0; i < 8; i++)
            red4(g_F1 + (size_t)rr[i] * 128 + lane * 4,
                 vv[i] * x[i].x, vv[i] * x[i].y, vv[i] * x[i].z, vv[i] * x[i].w);
    } else {
        for (int e = e0; e < nnz; e++) {
            int r = __ldg(er + e), c = __ldg(ec + e);
            float v = __ldg(ev + e);
            float4 x = *(const float4*)(g_H0 + (size_t)c * 128 + lane * 4);
            red4(g_F1 + (size_t)r * 128 + lane * 4, v * x.x, v * x.y, v * x.z, v * x.w);
        }
    }
}

__global__ void k_spmm64(const int* __restrict__ er, const int* __restrict__ ec,
                         const float* __restrict__ ev, int nnz)
{
    int idx = blockIdx.x * blockDim.x + threadIdx.x;
    int hw = idx >> 4;
    int l = idx & 15;
    int e0 = hw * 8;
    if (e0 >= nnz) return;
    if (e0 + 8 <= nnz) {
        int4 ra = *(const int4*)(er + e0), rb = *(const int4*)(er + e0 + 4);
        int4 ca = *(const int4*)(ec + e0), cb = *(const int4*)(ec + e0 + 4);
        float4 va = *(const float4*)(ev + e0), vb = *(const float4*)(ev + e0 + 4);
        int rr[8] = {ra.x, ra.y, ra.z, ra.w, rb.x, rb.y, rb.z, rb.w};
        int cc[8] = {ca.x, ca.y, ca.z, ca.w, cb.x, cb.y, cb.z, cb.w};
        float vv[8] = {va.x, va.y, va.z, va.w, vb.x, vb.y, vb.z, vb.w};
        float4 x[8];
#pragma unroll
        for (int i = 0; i < 8; i++)
            x[i] = *(const float4*)(g_H1 + (size_t)cc[i] * 64 + l * 4);
#pragma unroll
        for (int i = 0; i < 8; i++)
            red4(g_F2 + (size_t)rr[i] * 64 + l * 4,
                 vv[i] * x[i].x, vv[i] * x[i].y, vv[i] * x[i].z, vv[i] * x[i].w);
    } else {
        for (int e = e0; e < nnz; e++) {
            int r = __ldg(er + e), c = __ldg(ec + e);
            float v = __ldg(ev + e);
            float4 x = *(const float4*)(g_H1 + (size_t)c * 64 + l * 4);
            red4(g_F2 + (size_t)r * 64 + l * 4, v * x.x, v * x.y, v * x.z, v * x.w);
        }
    }
}

// ============================================================================
// Fused MLP head: layer1 (896->64) bf16x3 mma (R11 config), layers 2/3 FFMA.
// ============================================================================
__global__ __launch_bounds__(256, 2) void k_mlp_mma(
    const int* __restrict__ uIdx, const int* __restrict__ itIdx,
    const float* __restrict__ uE, const float* __restrict__ iE,
    const float* __restrict__ T1b,
    const float* __restrict__ T2W, const float* __restrict__ T2b,
    const float* __restrict__ T3W, const float* __restrict__ T3b,
    float* __restrict__ out, int B)
{
    constexpr int SR = 232;
    constexpr int ABUF = 64 * SR;
    constexpr int OFF_SU = 2 * ABUF * 2;
    constexpr int OFF_SI = OFF_SU + 256;
    constexpr int HSR = 65;
    constexpr int OFF_T2 = 64 * HSR * 4 + 64;
    constexpr int OFF_PART = OFF_T2 + 32 * 64 * 4;
    extern __shared__ __align__(16) char smem[];
    __nv_bfloat16* sA = (__nv_bfloat16*)smem;
    const u32 sbase = smem_u32(smem);
    int* su = (int*)(smem + OFF_SU);
    int* si = (int*)(smem + OFF_SI);

    const int t = threadIdx.x, wid = t >> 5, lane = t & 31;
    const int wm = wid >> 2, wn = wid & 3;
    const int rb = blockIdx.x * 64;

    if (t < 64) {
        int br = rb + t;
        su[t] = (br < B) ? uIdx[br] : 0;
        si[t] = (br < B) ? itIdx[br] : 0;
    }

    float acc[2][2][4];
#pragma unroll
    for (int mt = 0; mt < 2; mt++)
#pragma unroll
        for (int j = 0; j < 2; j++)
#pragma unroll
            for (int q = 0; q < 4; q++) acc[mt][j][q] = 0.f;

    const int arow = lane & 15;
    const int kshift = (lane >> 4) * 8;

    for (int chunk = 0; chunk < 4; chunk++) {
        const int kb = chunk * 224;
        __syncthreads();
#pragma unroll
        for (int it = 0; it < 14; it++) {
            int fid = t + it * 256;
            int r = fid / 56;
            int c4 = (fid % 56) * 4;
            int kg = kb + c4;
            const float* src; int stride, off, rowi;
            if (kg < 256)      { src = uE;   stride = 256; off = kg;       rowi = su[r]; }
            else if (kg < 384) { src = g_F1; stride = 128; off = kg - 256; rowi = su[r]; }
            else if (kg < 448) { src = g_F2; stride = 64;  off = kg - 384; rowi = su[r]; }
            else if (kg < 704) { src = iE;   stride = 256; off = kg - 448; rowi = si[r]; }
            else if (kg < 832) { src = g_F1; stride = 128; off = kg - 704; rowi = si[r] + U_NUM; }
            else               { src = g_F2; stride = 64;  off = kg - 832; rowi = si[r] + U_NUM; }
            float4 v = *(const float4*)(src + (size_t)rowi * stride + off);
            u32 h01, l01, h23, l23;
            split2(v.x, v.y, h01, l01);
            split2(v.z, v.w, h23, l23);
            int so = r * SR + c4;
            *(uint2*)(sA + so)        = make_uint2(h01, h23);
            *(uint2*)(sA + ABUF + so) = make_uint2(l01, l23);
        }
        __syncthreads();

#pragma unroll 2
        for (int ks2 = 0; ks2 < 14; ks2++) {
            const int ks = chunk * 14 + ks2;
            uint4 bw[2];
#pragma unroll
            for (int j = 0; j < 2; j++) {
                int nt = wn * 2 + j;
                bw[j] = __ldg(g_t1f + ((u32)(ks * 8 + nt)) * 32 + lane);
            }
            u32 a[2][2][4];
#pragma unroll
            for (int v = 0; v < 2; v++)
#pragma unroll
                for (int mt = 0; mt < 2; mt++) {
                    int row = wm * 32 + mt * 16 + arow;
                    u32 addr = sbase + (u32)((v * ABUF + row * SR + ks2 * 16 + kshift) * 2);
                    ldm4(a[v][mt], addr);
                }
#pragma unroll
            for (int mt = 0; mt < 2; mt++)
#pragma unroll
                for (int j = 0; j < 2; j++) {
                    mma16816(acc[mt][j], a[0][mt], bw[j].x, bw[j].y);
                    mma16816(acc[mt][j], a[0][mt], bw[j].z, bw[j].w);
                    mma16816(acc[mt][j], a[1][mt], bw[j].x, bw[j].y);
                }
        }
    }
    __syncthreads();

    float* Hs = (float*)smem;
    float* T2s = (float*)(smem + OFF_T2);
    float* part = (float*)(smem + OFF_PART);
    {
        const int rr = wm * 32 + (lane >> 2);
        const int cc = wn * 16 + (lane & 3) * 2;
#pragma unroll
        for (int mt = 0; mt < 2; mt++)
#pragma unroll
            for (int j = 0; j < 2; j++) {
                int c = cc + j * 8;
                float tb0 = __ldg(T1b + c), tb1 = __ldg(T1b + c + 1);
#pragma unroll
                for (int half = 0; half < 2; half++) {
                    int r = rr + mt * 16 + half * 8;
                    Hs[r * HSR + c]     = fmaxf(acc[mt][j][half * 2] + tb0, 0.f);
                    Hs[r * HSR + c + 1] = fmaxf(acc[mt][j][half * 2 + 1] + tb1, 0.f);
                }
            }
    }
#pragma unroll
    for (int i = 0; i < 2; i++) {
        int idx = t + i * 256;
        ((float4*)T2s)[idx] = ((const float4*)T2W)[idx];
    }
    __syncthreads();

    {
        int r = t & 63, g = t >> 6;
        float p = 0.f;
#pragma unroll
        for (int j = 0; j < 8; j++) {
            int c2 = g * 8 + j;
            float s = T2b[c2];
#pragma unroll
            for (int k = 0; k < 64; k++) s += Hs[r * HSR + k] * T2s[c2 * 64 + k];
            p += fmaxf(s, 0.f) * T3W[c2];
        }
        part[g * 64 + r] = p;
    }
    __syncthreads();
    if (t < 64) {
        int br = rb + t;
        if (br < B)
            out[br] = part[t] + part[64 + t] + part[128 + t] + part[192 + t] + T3b[0];
    }
}

// ============================================================================
extern "C" void kernel_launch(void* const* d_in, const int* in_sizes, int n_in,
                              void* d_out, int out_size)
{
    const int*   userIdx = (const int*)d_in[0];
    const int*   itemIdx = (const int*)d_in[1];
    const int*   er      = (const int*)d_in[2];
    const int*   ec      = (const int*)d_in[3];
    const float* ev      = (const float*)d_in[4];
    const float* uE      = (const float*)d_in[5];
    const float* iE      = (const float*)d_in[6];
    const float* W1_0    = (const float*)d_in[7];
    const float* b1_0    = (const float*)d_in[8];
    const float* W2_0    = (const float*)d_in[9];
    const float* b2_0    = (const float*)d_in[10];
    const float* W1_1    = (const float*)d_in[11];
    const float* b1_1    = (const float*)d_in[12];
    const float* W2_1    = (const float*)d_in[13];
    const float* b2_1    = (const float*)d_in[14];
    const float* T1W     = (const float*)d_in[15];
    const float* T1b     = (const float*)d_in[16];
    const float* T2W     = (const float*)d_in[17];
    const float* T2b     = (const float*)d_in[18];
    const float* T3W     = (const float*)d_in[19];
    const float* T3b     = (const float*)d_in[20];
    float* out = (float*)d_out;

    const int B   = in_sizes[0];
    const int nnz = in_sizes[2];

    constexpr int SMEM0 = 2 * 64 * (128 + 8) * 2;    // 34816, OCC=2
    constexpr int SMEM1 = 2 * 64 * (64 + 8) * 2;     // 18432, OCC=4
    constexpr int SMEMM = 2 * 64 * 232 * 2 + 1024;   // 60416, OCC=2
    static bool attr_done = false;
    if (!attr_done) {
        cudaFuncSetAttribute((const void*)k_gemm_mma<256, 2, 64, 128, 256, 128, 0, 2, 4>,
                             cudaFuncAttributeMaxDynamicSharedMemorySize, SMEM0);
        cudaFuncSetAttribute((const void*)k_gemm_mma<128, 4, 64, 64, 128, 64, 1, 2, 2>,
                             cudaFuncAttributeMaxDynamicSharedMemorySize, SMEM1);
        cudaFuncSetAttribute((const void*)k_mlp_mma,
                             cudaFuncAttributeMaxDynamicSharedMemorySize, SMEMM);
        attr_done = true;
    }

    // launch order: idx0=prep0, idx1=prep1, idx2=prep2, idx3=GEMM0 (profiled)
    k_prep0<<<32, 256>>>(W1_0, W2_0);
    k_prep1<<<8, 256>>>(W1_1, W2_1);
    k_prep2<<<56, 256>>>(T1W);

    k_gemm_mma<256, 2, 64, 128, 256, 128, 0, 2, 4>
        <<<(NTOT + 63) / 64, 256, SMEM0>>>(uE, iE, b1_0, b2_0);

    {
        long long warps = ((long long)nnz + 7) / 8;
        int blocks = (int)((warps * 32 + 255) / 256);
        k_spmm128<<<blocks, 256>>>(er, ec, ev, nnz);
    }

    k_gemm_mma<128, 4, 64, 64, 128, 64, 1, 2, 2>
        <<<(NTOT + 63) / 64, 128, SMEM1>>>(uE, iE, b1_1, b2_1);

    {
        long long hws = ((long long)nnz + 7) / 8;
        int blocks = (int)((hws * 16 + 255) / 256);
        k_spmm64<<<blocks, 256>>>(er, ec, ev, nnz);
    }

    k_mlp_mma<<<(B + 63) / 64, 256, SMEMM>>>(userIdx, itemIdx, uE, iE,
                                             T1b, T2W, T2b, T3W, T3b, out, B);
}

// round 16
// speedup vs baseline: 1.1391x; 1.0331x over previous
#include <cuda_runtime.h>
#include <cuda_bf16.h>
#include <cstdint>

#define U_NUM 30000
#define NTOT  100000

typedef unsigned long long u64;
typedef unsigned int u32;

// ---------------- scratch (device globals; allocation-free) ----------------
__device__ __align__(256) float g_H0[(size_t)NTOT * 128];
__device__ __align__(256) float g_F1[(size_t)NTOT * 128];
__device__ __align__(256) float g_H1[(size_t)NTOT * 64];
__device__ __align__(256) float g_F2[(size_t)NTOT * 64];
// main-path weights: uint4 = {hi01, hi23, lo01, lo23} per [ks][nt][lane]
__device__ __align__(256) uint4 g_w10f[16 * 16 * 32];
__device__ __align__(256) uint4 g_w11f[8 * 8 * 32];
__device__ __align__(256) uint4 g_t1f[56 * 8 * 32];
// square-path weights: DENSE uint2 = {hi01, hi23} per [ks][nt][lane]
__device__ __align__(256) uint2 g_w20d[16 * 16 * 32];
__device__ __align__(256) uint2 g_w21d[8 * 8 * 32];

// ---------------- helpers ----------------
__device__ __forceinline__ u32 smem_u32(const void* p) {
    u32 a;
    asm("{ .reg .u64 t; cvta.to.shared.u64 t, %1; cvt.u32.u64 %0, t; }" : "=r"(a) : "l"(p));
    return a;
}
__device__ __forceinline__ void ldm4(u32* r, u32 addr) {
    asm volatile("ldmatrix.sync.aligned.m8n8.x4.shared.b16 {%0,%1,%2,%3}, [%4];"
                 : "=r"(r[0]), "=r"(r[1]), "=r"(r[2]), "=r"(r[3]) : "r"(addr));
}
__device__ __forceinline__ void mma16816(float* c, const u32* a, u32 b0, u32 b1) {
    asm volatile("mma.sync.aligned.m16n8k16.row.col.f32.bf16.bf16.f32 "
                 "{%0,%1,%2,%3}, {%4,%5,%6,%7}, {%8,%9}, {%0,%1,%2,%3};"
                 : "+f"(c[0]), "+f"(c[1]), "+f"(c[2]), "+f"(c[3])
                 : "r"(a[0]), "r"(a[1]), "r"(a[2]), "r"(a[3]), "r"(b0), "r"(b1));
}
__device__ __forceinline__ void split2(float a, float b, u32& hi, u32& lo) {
    __nv_bfloat162 h = __floats2bfloat162_rn(a, b);
    float2 hf = __bfloat1622float2(h);
    __nv_bfloat162 l = __floats2bfloat162_rn(a - hf.x, b - hf.y);
    hi = *reinterpret_cast<u32*>(&h);
    lo = *reinterpret_cast<u32*>(&l);
}
__device__ __forceinline__ u32 sq_bf16x2(u32 x) {
    __nv_bfloat162 h = *reinterpret_cast<__nv_bfloat162*>(&x);
    __nv_bfloat162 s = __hmul2(h, h);
    return *reinterpret_cast<u32*>(&s);
}
__device__ __forceinline__ void red4(float* p, float a, float b, float c, float d) {
    asm volatile("{ .reg .u64 q; cvta.to.global.u64 q, %0; red.global.add.v4.f32 [q], {%1,%2,%3,%4}; }"
                 :: "l"(p), "f"(a), "f"(b), "f"(c), "f"(d) : "memory");
}

// ============================================================================
// Weight fragment prep (single kernel)
// ============================================================================
__device__ __forceinline__ void pack_frag4(const float* __restrict__ W, uint4* __restrict__ dst,
                                           int ks, int nt, int lane, int NT, int K)
{
    int n = nt * 8 + (lane >> 2);
    int k = ks * 16 + (lane & 3) * 2;
    const float* p = W + (size_t)n * K + k;
    float x0 = p[0], x1 = p[1], x2 = p[8], x3 = p[9];
    u32 h01, l01, h23, l23;
    split2(x0, x1, h01, l01);
    split2(x2, x3, h23, l23);
    dst[((size_t)ks * NT + nt) * 32 + lane] = make_uint4(h01, h23, l01, l23);
}
__device__ __forceinline__ void pack_frag2(const float* __restrict__ W, uint2* __restrict__ dst,
                                           int ks, int nt, int lane, int NT, int K)
{
    int n = nt * 8 + (lane >> 2);
    int k = ks * 16 + (lane & 3) * 2;
    const float* p = W + (size_t)n * K + k;
    __nv_bfloat162 h01 = __floats2bfloat162_rn(p[0], p[1]);
    __nv_bfloat162 h23 = __floats2bfloat162_rn(p[8], p[9]);
    dst[((size_t)ks * NT + nt) * 32 + lane] =
        make_uint2(*reinterpret_cast<u32*>(&h01), *reinterpret_cast<u32*>(&h23));
}

__global__ void k_prep(const float* __restrict__ W10, const float* __restrict__ W20,
                       const float* __restrict__ W11, const float* __restrict__ W21,
                       const float* __restrict__ T1W)
{
    int i = blockIdx.x * 256 + threadIdx.x;
    if (i < 8192) {                        // layer0: KS=16, NT=16
        int lane = i & 31, nt = (i >> 5) & 15, ks = i >> 9;
        pack_frag4(W10, g_w10f, ks, nt, lane, 16, 256);
        pack_frag2(W20, g_w20d, ks, nt, lane, 16, 256);
    } else if (i < 10240) {                // layer1: KS=8, NT=8
        int j = i - 8192;
        int lane = j & 31, nt = (j >> 5) & 7, ks = j >> 8;
        pack_frag4(W11, g_w11f, ks, nt, lane, 8, 128);
        pack_frag2(W21, g_w21d, ks, nt, lane, 8, 128);
    } else if (i < 24576) {                // T1: KS=56, NT=8
        int j = i - 10240;
        int lane = j & 31, nt = (j >> 5) & 7, ks = j >> 8;
        pack_frag4(T1W, g_t1f, ks, nt, lane, 8, 896);
    }
}

// ============================================================================
// Fused dual GEMM: main path bf16x3 compensated; square path plain bf16 with
// A fragment derived in registers and DENSE uint2 weight table.
//   Fout = A@W1^T + (b1+b2),  Hout = A@W1^T + (A*A)@W2^T
// ============================================================================
template<int THREADS, int OCC, int BM, int DOUT, int KTOT, int CHUNK,
         int MODE, int WM_N, int WN_N>
__global__ __launch_bounds__(THREADS, OCC) void k_gemm_mma(
    const float* __restrict__ uE, const float* __restrict__ iE,
    const float* __restrict__ b1, const float* __restrict__ b2)
{
    constexpr int SR = CHUNK + 8;
    constexpr int ABUF = BM * SR;
    constexpr int NCH = KTOT / CHUNK;
    constexpr int KS_C = CHUNK / 16;
    constexpr int NT = DOUT / 8;
    constexpr int JW = NT / WN_N;
    constexpr int F4R = CHUNK / 4;
    extern __shared__ __align__(16) char smem[];
    __nv_bfloat16* sA = (__nv_bfloat16*)smem;
    const u32 sbase = smem_u32(smem);

    const uint4* __restrict__ w1f = (MODE == 0) ? g_w10f : g_w11f;
    const uint2* __restrict__ w2f = (MODE == 0) ? g_w20d : g_w21d;
    float* __restrict__ Fout = (MODE == 0) ? g_F1 : g_F2;
    float* __restrict__ Hout = (MODE == 0) ? g_H0 : g_H1;

    const int t = threadIdx.x, wid = t >> 5, lane = t & 31;
    const int wm = wid / WN_N, wn = wid % WN_N;
    const int row0 = blockIdx.x * BM;

    float acc1[2][JW][4], acc2[2][JW][4];
#pragma unroll
    for (int mt = 0; mt < 2; mt++)
#pragma unroll
        for (int j = 0; j < JW; j++)
#pragma unroll
            for (int q = 0; q < 4; q++) { acc1[mt][j][q] = 0.f; acc2[mt][j][q] = 0.f; }

    const int arow = lane & 15;
    const int kshift = (lane >> 4) * 8;

    for (int ch = 0; ch < NCH; ch++) {
        __syncthreads();
#pragma unroll
        for (int it = 0; it < BM * F4R / THREADS; it++) {
            int fid = t + it * THREADS;
            int r = fid / F4R;
            int c4 = (fid % F4R) * 4;
            int gr = row0 + r;
            float4 v = make_float4(0.f, 0.f, 0.f, 0.f);
            if (gr < NTOT) {
                const float* src;
                if (MODE == 0) src = (gr < U_NUM) ? uE + (size_t)gr * 256
                                                  : iE + (size_t)(gr - U_NUM) * 256;
                else           src = g_F1 + (size_t)gr * 128;
                v = *(const float4*)(src + ch * CHUNK + c4);
            }
            u32 h01, l01, h23, l23;
            split2(v.x, v.y, h01, l01);
            split2(v.z, v.w, h23, l23);
            int off = r * SR + c4;
            *(uint2*)(sA + off)        = make_uint2(h01, h23);
            *(uint2*)(sA + ABUF + off) = make_uint2(l01, l23);
        }
        __syncthreads();

#pragma unroll 2
        for (int ks2 = 0; ks2 < KS_C; ks2++) {
            const int ks = ch * KS_C + ks2;
            u32 a[2][2][4];
#pragma unroll
            for (int v = 0; v < 2; v++)
#pragma unroll
                for (int mt = 0; mt < 2; mt++) {
                    int row = wm * 32 + mt * 16 + arow;
                    u32 addr = sbase + (u32)((v * ABUF + row * SR + ks2 * 16 + kshift) * 2);
                    ldm4(a[v][mt], addr);
                }
            u32 asq[2][4];
#pragma unroll
            for (int mt = 0; mt < 2; mt++)
#pragma unroll
                for (int i = 0; i < 4; i++)
                    asq[mt][i] = sq_bf16x2(a[0][mt][i]);

#pragma unroll
            for (int h = 0; h < (JW + 1) / 2; h++) {
                constexpr int JH = (JW >= 2) ? 2 : 1;
                uint4 bw1[JH];
                uint2 bw2[JH];
#pragma unroll
                for (int jj = 0; jj < JH; jj++) {
                    int nt = wn * JW + h * JH + jj;
                    u32 idx = ((u32)(ks * NT + nt)) * 32 + lane;
                    bw1[jj] = __ldg(w1f + idx);
                    bw2[jj] = __ldg(w2f + idx);          // dense table
                }
#pragma unroll
                for (int mt = 0; mt < 2; mt++)
#pragma unroll
                    for (int jj = 0; jj < JH; jj++) {
                        int j = h * JH + jj;
                        mma16816(acc1[mt][j], a[0][mt], bw1[jj].x, bw1[jj].y);
                        mma16816(acc1[mt][j], a[0][mt], bw1[jj].z, bw1[jj].w);
                        mma16816(acc1[mt][j], a[1][mt], bw1[jj].x, bw1[jj].y);
                        mma16816(acc2[mt][j], asq[mt],  bw2[jj].x, bw2[jj].y);
                    }
            }
        }
    }

    const int r_base = row0 + wm * 32 + (lane >> 2);
    const int c_base = wn * (JW * 8) + (lane & 3) * 2;
#pragma unroll
    for (int mt = 0; mt < 2; mt++)
#pragma unroll
        for (int j = 0; j < JW; j++) {
            int c = c_base + j * 8;
            float bs0 = __ldg(b1 + c) + __ldg(b2 + c);
            float bs1 = __ldg(b1 + c + 1) + __ldg(b2 + c + 1);
#pragma unroll
            for (int half = 0; half < 2; half++) {
                int r = r_base + mt * 16 + half * 8;
                if (r < NTOT) {
                    float a0 = acc1[mt][j][half * 2], a1 = acc1[mt][j][half * 2 + 1];
                    float2 f = make_float2(a0 + bs0, a1 + bs1);
                    float2 h2 = make_float2(a0 + acc2[mt][j][half * 2],
                                            a1 + acc2[mt][j][half * 2 + 1]);
                    *(float2*)(Fout + (size_t)r * DOUT + c) = f;
                    *(float2*)(Hout + (size_t)r * DOUT + c) = h2;
                }
            }
        }
}

// ============================================================================
// SpMM scatter: F[row] += val * H[col].  8 edges per (sub)warp.
// ============================================================================
__global__ void k_spmm128(const int* __restrict__ er, const int* __restrict__ ec,
                          const float* __restrict__ ev, int nnz)
{
    int w = (blockIdx.x * blockDim.x + threadIdx.x) >> 5;
    int lane = threadIdx.x & 31;
    int e0 = w * 8;
    if (e0 >= nnz) return;
    if (e0 + 8 <= nnz) {
        int4 ra = *(const int4*)(er + e0), rb = *(const int4*)(er + e0 + 4);
        int4 ca = *(const int4*)(ec + e0), cb = *(const int4*)(ec + e0 + 4);
        float4 va = *(const float4*)(ev + e0), vb = *(const float4*)(ev + e0 + 4);
        int rr[8] = {ra.x, ra.y, ra.z, ra.w, rb.x, rb.y, rb.z, rb.w};
        int cc[8] = {ca.x, ca.y, ca.z, ca.w, cb.x, cb.y, cb.z, cb.w};
        float vv[8] = {va.x, va.y, va.z, va.w, vb.x, vb.y, vb.z, vb.w};
        float4 x[8];
#pragma unroll
        for (int i = 0; i < 8; i++)
            x[i] = *(const float4*)(g_H0 + (size_t)cc[i] * 128 + lane * 4);
#pragma unroll
        for (int i = 0; i < 8; i++)
            red4(g_F1 + (size_t)rr[i] * 128 + lane * 4,
                 vv[i] * x[i].x, vv[i] * x[i].y, vv[i] * x[i].z, vv[i] * x[i].w);
    } else {
        for (int e = e0; e < nnz; e++) {
            int r = __ldg(er + e), c = __ldg(ec + e);
            float v = __ldg(ev + e);
            float4 x = *(const float4*)(g_H0 + (size_t)c * 128 + lane * 4);
            red4(g_F1 + (size_t)r * 128 + lane * 4, v * x.x, v * x.y, v * x.z, v * x.w);
        }
    }
}

__global__ void k_spmm64(const int* __restrict__ er, const int* __restrict__ ec,
                         const float* __restrict__ ev, int nnz)
{
    int idx = blockIdx.x * blockDim.x + threadIdx.x;
    int hw = idx >> 4;
    int l = idx & 15;
    int e0 = hw * 8;
    if (e0 >= nnz) return;
    if (e0 + 8 <= nnz) {
        int4 ra = *(const int4*)(er + e0), rb = *(const int4*)(er + e0 + 4);
        int4 ca = *(const int4*)(ec + e0), cb = *(const int4*)(ec + e0 + 4);
        float4 va = *(const float4*)(ev + e0), vb = *(const float4*)(ev + e0 + 4);
        int rr[8] = {ra.x, ra.y, ra.z, ra.w, rb.x, rb.y, rb.z, rb.w};
        int cc[8] = {ca.x, ca.y, ca.z, ca.w, cb.x, cb.y, cb.z, cb.w};
        float vv[8] = {va.x, va.y, va.z, va.w, vb.x, vb.y, vb.z, vb.w};
        float4 x[8];
#pragma unroll
        for (int i = 0; i < 8; i++)
            x[i] = *(const float4*)(g_H1 + (size_t)cc[i] * 64 + l * 4);
#pragma unroll
        for (int i = 0; i < 8; i++)
            red4(g_F2 + (size_t)rr[i] * 64 + l * 4,
                 vv[i] * x[i].x, vv[i] * x[i].y, vv[i] * x[i].z, vv[i] * x[i].w);
    } else {
        for (int e = e0; e < nnz; e++) {
            int r = __ldg(er + e), c = __ldg(ec + e);
            float v = __ldg(ev + e);
            float4 x = *(const float4*)(g_H1 + (size_t)c * 64 + l * 4);
            red4(g_F2 + (size_t)r * 64 + l * 4, v * x.x, v * x.y, v * x.z, v * x.w);
        }
    }
}

// ============================================================================
// Fused MLP head: layer1 (896->64) bf16x3 mma, layers 2/3 FFMA.
// ============================================================================
__global__ __launch_bounds__(256, 2) void k_mlp_mma(
    const int* __restrict__ uIdx, const int* __restrict__ itIdx,
    const float* __restrict__ uE, const float* __restrict__ iE,
    const float* __restrict__ T1b,
    const float* __restrict__ T2W, const float* __restrict__ T2b,
    const float* __restrict__ T3W, const float* __restrict__ T3b,
    float* __restrict__ out, int B)
{
    constexpr int SR = 232;
    constexpr int ABUF = 64 * SR;
    constexpr int OFF_SU = 2 * ABUF * 2;
    constexpr int OFF_SI = OFF_SU + 256;
    constexpr int HSR = 65;
    constexpr int OFF_T2 = 64 * HSR * 4 + 64;
    constexpr int OFF_PART = OFF_T2 + 32 * 64 * 4;
    extern __shared__ __align__(16) char smem[];
    __nv_bfloat16* sA = (__nv_bfloat16*)smem;
    const u32 sbase = smem_u32(smem);
    int* su = (int*)(smem + OFF_SU);
    int* si = (int*)(smem + OFF_SI);

    const int t = threadIdx.x, wid = t >> 5, lane = t & 31;
    const int wm = wid >> 2, wn = wid & 3;
    const int rb = blockIdx.x * 64;

    if (t < 64) {
        int br = rb + t;
        su[t] = (br < B) ? uIdx[br] : 0;
        si[t] = (br < B) ? itIdx[br] : 0;
    }

    float acc[2][2][4];
#pragma unroll
    for (int mt = 0; mt < 2; mt++)
#pragma unroll
        for (int j = 0; j < 2; j++)
#pragma unroll
            for (int q = 0; q < 4; q++) acc[mt][j][q] = 0.f;

    const int arow = lane & 15;
    const int kshift = (lane >> 4) * 8;

    for (int chunk = 0; chunk < 4; chunk++) {
        const int kb = chunk * 224;
        __syncthreads();
#pragma unroll
        for (int it = 0; it < 14; it++) {
            int fid = t + it * 256;
            int r = fid / 56;
            int c4 = (fid % 56) * 4;
            int kg = kb + c4;
            const float* src; int stride, off, rowi;
            if (kg < 256)      { src = uE;   stride = 256; off = kg;       rowi = su[r]; }
            else if (kg < 384) { src = g_F1; stride = 128; off = kg - 256; rowi = su[r]; }
            else if (kg < 448) { src = g_F2; stride = 64;  off = kg - 384; rowi = su[r]; }
            else if (kg < 704) { src = iE;   stride = 256; off = kg - 448; rowi = si[r]; }
            else if (kg < 832) { src = g_F1; stride = 128; off = kg - 704; rowi = si[r] + U_NUM; }
            else               { src = g_F2; stride = 64;  off = kg - 832; rowi = si[r] + U_NUM; }
            float4 v = *(const float4*)(src + (size_t)rowi * stride + off);
            u32 h01, l01, h23, l23;
            split2(v.x, v.y, h01, l01);
            split2(v.z, v.w, h23, l23);
            int so = r * SR + c4;
            *(uint2*)(sA + so)        = make_uint2(h01, h23);
            *(uint2*)(sA + ABUF + so) = make_uint2(l01, l23);
        }
        __syncthreads();

#pragma unroll 2
        for (int ks2 = 0; ks2 < 14; ks2++) {
            const int ks = chunk * 14 + ks2;
            uint4 bw[2];
#pragma unroll
            for (int j = 0; j < 2; j++) {
                int nt = wn * 2 + j;
                bw[j] = __ldg(g_t1f + ((u32)(ks * 8 + nt)) * 32 + lane);
            }
            u32 a[2][2][4];
#pragma unroll
            for (int v = 0; v < 2; v++)
#pragma unroll
                for (int mt = 0; mt < 2; mt++) {
                    int row = wm * 32 + mt * 16 + arow;
                    u32 addr = sbase + (u32)((v * ABUF + row * SR + ks2 * 16 + kshift) * 2);
                    ldm4(a[v][mt], addr);
                }
#pragma unroll
            for (int mt = 0; mt < 2; mt++)
#pragma unroll
                for (int j = 0; j < 2; j++) {
                    mma16816(acc[mt][j], a[0][mt], bw[j].x, bw[j].y);
                    mma16816(acc[mt][j], a[0][mt], bw[j].z, bw[j].w);
                    mma16816(acc[mt][j], a[1][mt], bw[j].x, bw[j].y);
                }
        }
    }
    __syncthreads();

    float* Hs = (float*)smem;
    float* T2s = (float*)(smem + OFF_T2);
    float* part = (float*)(smem + OFF_PART);
    {
        const int rr = wm * 32 + (lane >> 2);
        const int cc = wn * 16 + (lane & 3) * 2;
#pragma unroll
        for (int mt = 0; mt < 2; mt++)
#pragma unroll
            for (int j = 0; j < 2; j++) {
                int c = cc + j * 8;
                float tb0 = __ldg(T1b + c), tb1 = __ldg(T1b + c + 1);
#pragma unroll
                for (int half = 0; half < 2; half++) {
                    int r = rr + mt * 16 + half * 8;
                    Hs[r * HSR + c]     = fmaxf(acc[mt][j][half * 2] + tb0, 0.f);
                    Hs[r * HSR + c + 1] = fmaxf(acc[mt][j][half * 2 + 1] + tb1, 0.f);
                }
            }
    }
#pragma unroll
    for (int i = 0; i < 2; i++) {
        int idx = t + i * 256;
        ((float4*)T2s)[idx] = ((const float4*)T2W)[idx];
    }
    __syncthreads();

    {
        int r = t & 63, g = t >> 6;
        float p = 0.f;
#pragma unroll
        for (int j = 0; j < 8; j++) {
            int c2 = g * 8 + j;
            float s = T2b[c2];
#pragma unroll
            for (int k = 0; k < 64; k++) s += Hs[r * HSR + k] * T2s[c2 * 64 + k];
            p += fmaxf(s, 0.f) * T3W[c2];
        }
        part[g * 64 + r] = p;
    }
    __syncthreads();
    if (t < 64) {
        int br = rb + t;
        if (br < B)
            out[br] = part[t] + part[64 + t] + part[128 + t] + part[192 + t] + T3b[0];
    }
}

// ============================================================================
extern "C" void kernel_launch(void* const* d_in, const int* in_sizes, int n_in,
                              void* d_out, int out_size)
{
    const int*   userIdx = (const int*)d_in[0];
    const int*   itemIdx = (const int*)d_in[1];
    const int*   er      = (const int*)d_in[2];
    const int*   ec      = (const int*)d_in[3];
    const float* ev      = (const float*)d_in[4];
    const float* uE      = (const float*)d_in[5];
    const float* iE      = (const float*)d_in[6];
    const float* W1_0    = (const float*)d_in[7];
    const float* b1_0    = (const float*)d_in[8];
    const float* W2_0    = (const float*)d_in[9];
    const float* b2_0    = (const float*)d_in[10];
    const float* W1_1    = (const float*)d_in[11];
    const float* b1_1    = (const float*)d_in[12];
    const float* W2_1    = (const float*)d_in[13];
    const float* b2_1    = (const float*)d_in[14];
    const float* T1W     = (const float*)d_in[15];
    const float* T1b     = (const float*)d_in[16];
    const float* T2W     = (const float*)d_in[17];
    const float* T2b     = (const float*)d_in[18];
    const float* T3W     = (const float*)d_in[19];
    const float* T3b     = (const float*)d_in[20];
    float* out = (float*)d_out;

    const int B   = in_sizes[0];
    const int nnz = in_sizes[2];

    constexpr int SMEM0 = 2 * 64 * (128 + 8) * 2;    // 34816, OCC=2
    constexpr int SMEM1 = 2 * 64 * (64 + 8) * 2;     // 18432, OCC=4
    constexpr int SMEMM = 2 * 64 * 232 * 2 + 1024;   // 60416, OCC=2
    static bool attr_done = false;
    if (!attr_done) {
        cudaFuncSetAttribute((const void*)k_gemm_mma<256, 2, 64, 128, 256, 128, 0, 2, 4>,
                             cudaFuncAttributeMaxDynamicSharedMemorySize, SMEM0);
        cudaFuncSetAttribute((const void*)k_gemm_mma<128, 4, 64, 64, 128, 64, 1, 2, 2>,
                             cudaFuncAttributeMaxDynamicSharedMemorySize, SMEM1);
        cudaFuncSetAttribute((const void*)k_mlp_mma,
                             cudaFuncAttributeMaxDynamicSharedMemorySize, SMEMM);
        attr_done = true;
    }

    k_prep<<<96, 256>>>(W1_0, W2_0, W1_1, W2_1, T1W);

    k_gemm_mma<256, 2, 64, 128, 256, 128, 0, 2, 4>
        <<<(NTOT + 63) / 64, 256, SMEM0>>>(uE, iE, b1_0, b2_0);

    {
        long long warps = ((long long)nnz + 7) / 8;
        int blocks = (int)((warps * 32 + 255) / 256);
        k_spmm128<<<blocks, 256>>>(er, ec, ev, nnz);
    }

    k_gemm_mma<128, 4, 64, 64, 128, 64, 1, 2, 2>
        <<<(NTOT + 63) / 64, 128, SMEM1>>>(uE, iE, b1_1, b2_1);

    {
        long long hws = ((long long)nnz + 7) / 8;
        int blocks = (int)((hws * 16 + 255) / 256);
        k_spmm64<<<blocks, 256>>>(er, ec, ev, nnz);
    }

    k_mlp_mma<<<(B + 63) / 64, 256, SMEMM>>>(userIdx, itemIdx, uE, iE,
                                             T1b, T2W, T2b, T3W, T3b, out, B);
}

// round 17
// speedup vs baseline: 1.1894x; 1.0442x over previous
#include <cuda_runtime.h>
#include <cuda_bf16.h>
#include <cstdint>

#define U_NUM 30000
#define NTOT  100000

typedef unsigned long long u64;
typedef unsigned int u32;

// ---------------- scratch (device globals; allocation-free) ----------------
__device__ __align__(256) float g_H0[(size_t)NTOT * 128];
__device__ __align__(256) float g_F1[(size_t)NTOT * 128];
__device__ __align__(256) float g_H1[(size_t)NTOT * 64];
__device__ __align__(256) float g_F2[(size_t)NTOT * 64];
// main-path weights, [nt][ks][lane] streaming order: uint4 = {hi01,hi23,lo01,lo23}
__device__ __align__(256) uint4 g_w10f[16 * 16 * 32];
__device__ __align__(256) uint4 g_w11f[8 * 8 * 32];
__device__ __align__(256) uint4 g_t1f[8 * 56 * 32];
// square-path weights, dense uint2 {hi01,hi23}, [nt][ks][lane]
__device__ __align__(256) uint2 g_w20d[16 * 16 * 32];
__device__ __align__(256) uint2 g_w21d[8 * 8 * 32];

// ---------------- helpers ----------------
__device__ __forceinline__ u32 smem_u32(const void* p) {
    u32 a;
    asm("{ .reg .u64 t; cvta.to.shared.u64 t, %1; cvt.u32.u64 %0, t; }" : "=r"(a) : "l"(p));
    return a;
}
__device__ __forceinline__ void ldm4(u32* r, u32 addr) {
    asm volatile("ldmatrix.sync.aligned.m8n8.x4.shared.b16 {%0,%1,%2,%3}, [%4];"
                 : "=r"(r[0]), "=r"(r[1]), "=r"(r[2]), "=r"(r[3]) : "r"(addr));
}
__device__ __forceinline__ void mma16816(float* c, const u32* a, u32 b0, u32 b1) {
    asm volatile("mma.sync.aligned.m16n8k16.row.col.f32.bf16.bf16.f32 "
                 "{%0,%1,%2,%3}, {%4,%5,%6,%7}, {%8,%9}, {%0,%1,%2,%3};"
                 : "+f"(c[0]), "+f"(c[1]), "+f"(c[2]), "+f"(c[3])
                 : "r"(a[0]), "r"(a[1]), "r"(a[2]), "r"(a[3]), "r"(b0), "r"(b1));
}
__device__ __forceinline__ void split2(float a, float b, u32& hi, u32& lo) {
    __nv_bfloat162 h = __floats2bfloat162_rn(a, b);
    float2 hf = __bfloat1622float2(h);
    __nv_bfloat162 l = __floats2bfloat162_rn(a - hf.x, b - hf.y);
    hi = *reinterpret_cast<u32*>(&h);
    lo = *reinterpret_cast<u32*>(&l);
}
__device__ __forceinline__ u32 sq_bf16x2(u32 x) {
    __nv_bfloat162 h = *reinterpret_cast<__nv_bfloat162*>(&x);
    __nv_bfloat162 s = __hmul2(h, h);
    return *reinterpret_cast<u32*>(&s);
}
__device__ __forceinline__ void red4(float* p, float a, float b, float c, float d) {
    asm volatile("{ .reg .u64 q; cvta.to.global.u64 q, %0; red.global.add.v4.f32 [q], {%1,%2,%3,%4}; }"
                 :: "l"(p), "f"(a), "f"(b), "f"(c), "f"(d) : "memory");
}

// ============================================================================
// Weight fragment prep: [nt][ks][lane] streaming layout
// ============================================================================
__device__ __forceinline__ void pack_frag4(const float* __restrict__ W, uint4* __restrict__ dst,
                                           int ks, int nt, int lane, int KS, int K)
{
    int n = nt * 8 + (lane >> 2);
    int k = ks * 16 + (lane & 3) * 2;
    const float* p = W + (size_t)n * K + k;
    u32 h01, l01, h23, l23;
    split2(p[0], p[1], h01, l01);
    split2(p[8], p[9], h23, l23);
    dst[((size_t)nt * KS + ks) * 32 + lane] = make_uint4(h01, h23, l01, l23);
}
__device__ __forceinline__ void pack_frag2(const float* __restrict__ W, uint2* __restrict__ dst,
                                           int ks, int nt, int lane, int KS, int K)
{
    int n = nt * 8 + (lane >> 2);
    int k = ks * 16 + (lane & 3) * 2;
    const float* p = W + (size_t)n * K + k;
    __nv_bfloat162 h01 = __floats2bfloat162_rn(p[0], p[1]);
    __nv_bfloat162 h23 = __floats2bfloat162_rn(p[8], p[9]);
    dst[((size_t)nt * KS + ks) * 32 + lane] =
        make_uint2(*reinterpret_cast<u32*>(&h01), *reinterpret_cast<u32*>(&h23));
}

__global__ void k_prep(const float* __restrict__ W10, const float* __restrict__ W20,
                       const float* __restrict__ W11, const float* __restrict__ W21,
                       const float* __restrict__ T1W)
{
    int i = blockIdx.x * 256 + threadIdx.x;
    if (i < 8192) {                        // layer0: KS=16, NT=16
        int lane = i & 31, nt = (i >> 5) & 15, ks = i >> 9;
        pack_frag4(W10, g_w10f, ks, nt, lane, 16, 256);
        pack_frag2(W20, g_w20d, ks, nt, lane, 16, 256);
    } else if (i < 10240) {                // layer1: KS=8, NT=8
        int j = i - 8192;
        int lane = j & 31, nt = (j >> 5) & 7, ks = j >> 8;
        pack_frag4(W11, g_w11f, ks, nt, lane, 8, 128);
        pack_frag2(W21, g_w21d, ks, nt, lane, 8, 128);
    } else if (i < 24576) {                // T1: KS=56, NT=8
        int j = i - 10240;
        int lane = j & 31, nt = (j >> 5) & 7, ks = j >> 8;
        pack_frag4(T1W, g_t1f, ks, nt, lane, 56, 896);
    }
}

// ============================================================================
// Fused dual GEMM: main bf16x3 compensated; square path plain bf16 with
// in-register squared A fragment and dense [nt][ks] weight table.
//   Fout = A@W1^T + (b1+b2),  Hout = A@W1^T + (A*A)@W2^T
// ============================================================================
template<int THREADS, int OCC, int BM, int DOUT, int KTOT, int CHUNK,
         int MODE, int WM_N, int WN_N, int UNR>
__global__ __launch_bounds__(THREADS, OCC) void k_gemm_mma(
    const float* __restrict__ uE, const float* __restrict__ iE,
    const float* __restrict__ b1, const float* __restrict__ b2)
{
    constexpr int SR = CHUNK + 8;
    constexpr int ABUF = BM * SR;
    constexpr int NCH = KTOT / CHUNK;
    constexpr int KS_C = CHUNK / 16;
    constexpr int KS = KTOT / 16;
    constexpr int NT = DOUT / 8;
    constexpr int JW = NT / WN_N;
    constexpr int F4R = CHUNK / 4;
    extern __shared__ __align__(16) char smem[];
    __nv_bfloat16* sA = (__nv_bfloat16*)smem;
    const u32 sbase = smem_u32(smem);

    const uint4* __restrict__ w1f = (MODE == 0) ? g_w10f : g_w11f;
    const uint2* __restrict__ w2f = (MODE == 0) ? g_w20d : g_w21d;
    float* __restrict__ Fout = (MODE == 0) ? g_F1 : g_F2;
    float* __restrict__ Hout = (MODE == 0) ? g_H0 : g_H1;

    const int t = threadIdx.x, wid = t >> 5, lane = t & 31;
    const int wm = wid / WN_N, wn = wid % WN_N;
    const int row0 = blockIdx.x * BM;

    float acc1[2][JW][4], acc2[2][JW][4];
#pragma unroll
    for (int mt = 0; mt < 2; mt++)
#pragma unroll
        for (int j = 0; j < JW; j++)
#pragma unroll
            for (int q = 0; q < 4; q++) { acc1[mt][j][q] = 0.f; acc2[mt][j][q] = 0.f; }

    const int arow = lane & 15;
    const int kshift = (lane >> 4) * 8;

    for (int ch = 0; ch < NCH; ch++) {
        __syncthreads();
#pragma unroll
        for (int it = 0; it < BM * F4R / THREADS; it++) {
            int fid = t + it * THREADS;
            int r = fid / F4R;
            int c4 = (fid % F4R) * 4;
            int gr = row0 + r;
            float4 v = make_float4(0.f, 0.f, 0.f, 0.f);
            if (gr < NTOT) {
                const float* src;
                if (MODE == 0) src = (gr < U_NUM) ? uE + (size_t)gr * 256
                                                  : iE + (size_t)(gr - U_NUM) * 256;
                else           src = g_F1 + (size_t)gr * 128;
                v = *(const float4*)(src + ch * CHUNK + c4);
            }
            u32 h01, l01, h23, l23;
            split2(v.x, v.y, h01, l01);
            split2(v.z, v.w, h23, l23);
            int off = r * SR + c4;
            *(uint2*)(sA + off)        = make_uint2(h01, h23);
            *(uint2*)(sA + ABUF + off) = make_uint2(l01, l23);
        }
        __syncthreads();

#pragma unroll UNR
        for (int ks2 = 0; ks2 < KS_C; ks2++) {
            const int ks = ch * KS_C + ks2;
            u32 a[2][2][4];
#pragma unroll
            for (int v = 0; v < 2; v++)
#pragma unroll
                for (int mt = 0; mt < 2; mt++) {
                    int row = wm * 32 + mt * 16 + arow;
                    u32 addr = sbase + (u32)((v * ABUF + row * SR + ks2 * 16 + kshift) * 2);
                    ldm4(a[v][mt], addr);
                }
            u32 asq[2][4];
#pragma unroll
            for (int mt = 0; mt < 2; mt++)
#pragma unroll
                for (int i = 0; i < 4; i++)
                    asq[mt][i] = sq_bf16x2(a[0][mt][i]);

#pragma unroll
            for (int h = 0; h < (JW + 1) / 2; h++) {
                constexpr int JH = (JW >= 2) ? 2 : 1;
                uint4 bw1[JH];
                uint2 bw2[JH];
#pragma unroll
                for (int jj = 0; jj < JH; jj++) {
                    int nt = wn * JW + h * JH + jj;
                    u32 idx = ((u32)(nt * KS + ks)) * 32 + lane;   // [nt][ks] streaming
                    bw1[jj] = __ldg(w1f + idx);
                    bw2[jj] = __ldg(w2f + idx);
                }
#pragma unroll
                for (int mt = 0; mt < 2; mt++)
#pragma unroll
                    for (int jj = 0; jj < JH; jj++) {
                        int j = h * JH + jj;
                        mma16816(acc1[mt][j], a[0][mt], bw1[jj].x, bw1[jj].y);
                        mma16816(acc1[mt][j], a[0][mt], bw1[jj].z, bw1[jj].w);
                        mma16816(acc1[mt][j], a[1][mt], bw1[jj].x, bw1[jj].y);
                        mma16816(acc2[mt][j], asq[mt],  bw2[jj].x, bw2[jj].y);
                    }
            }
        }
    }

    const int r_base = row0 + wm * 32 + (lane >> 2);
    const int c_base = wn * (JW * 8) + (lane & 3) * 2;
#pragma unroll
    for (int mt = 0; mt < 2; mt++)
#pragma unroll
        for (int j = 0; j < JW; j++) {
            int c = c_base + j * 8;
            float bs0 = __ldg(b1 + c) + __ldg(b2 + c);
            float bs1 = __ldg(b1 + c + 1) + __ldg(b2 + c + 1);
#pragma unroll
            for (int half = 0; half < 2; half++) {
                int r = r_base + mt * 16 + half * 8;
                if (r < NTOT) {
                    float a0 = acc1[mt][j][half * 2], a1 = acc1[mt][j][half * 2 + 1];
                    float2 f = make_float2(a0 + bs0, a1 + bs1);
                    float2 h2 = make_float2(a0 + acc2[mt][j][half * 2],
                                            a1 + acc2[mt][j][half * 2 + 1]);
                    *(float2*)(Fout + (size_t)r * DOUT + c) = f;
                    *(float2*)(Hout + (size_t)r * DOUT + c) = h2;
                }
            }
        }
}

// ============================================================================
// SpMM scatter: F[row] += val * H[col].  8 edges per (sub)warp.
// ============================================================================
__global__ void k_spmm128(const int* __restrict__ er, const int* __restrict__ ec,
                          const float* __restrict__ ev, int nnz)
{
    int w = (blockIdx.x * blockDim.x + threadIdx.x) >> 5;
    int lane = threadIdx.x & 31;
    int e0 = w * 8;
    if (e0 >= nnz) return;
    if (e0 + 8 <= nnz) {
        int4 ra = *(const int4*)(er + e0), rb = *(const int4*)(er + e0 + 4);
        int4 ca = *(const int4*)(ec + e0), cb = *(const int4*)(ec + e0 + 4);
        float4 va = *(const float4*)(ev + e0), vb = *(const float4*)(ev + e0 + 4);
        int rr[8] = {ra.x, ra.y, ra.z, ra.w, rb.x, rb.y, rb.z, rb.w};
        int cc[8] = {ca.x, ca.y, ca.z, ca.w, cb.x, cb.y, cb.z, cb.w};
        float vv[8] = {va.x, va.y, va.z, va.w, vb.x, vb.y, vb.z, vb.w};
        float4 x[8];
#pragma unroll
        for (int i = 0; i < 8; i++)
            x[i] = *(const float4*)(g_H0 + (size_t)cc[i] * 128 + lane * 4);
#pragma unroll
        for (int i = 0; i < 8; i++)
            red4(g_F1 + (size_t)rr[i] * 128 + lane * 4,
                 vv[i] * x[i].x, vv[i] * x[i].y, vv[i] * x[i].z, vv[i] * x[i].w);
    } else {
        for (int e = e0; e < nnz; e++) {
            int r = __ldg(er + e), c = __ldg(ec + e);
            float v = __ldg(ev + e);
            float4 x = *(const float4*)(g_H0 + (size_t)c * 128 + lane * 4);
            red4(g_F1 + (size_t)r * 128 + lane * 4, v * x.x, v * x.y, v * x.z, v * x.w);
        }
    }
}

__global__ void k_spmm64(const int* __restrict__ er, const int* __restrict__ ec,
                         const float* __restrict__ ev, int nnz)
{
    int idx = blockIdx.x * blockDim.x + threadIdx.x;
    int hw = idx >> 4;
    int l = idx & 15;
    int e0 = hw * 8;
    if (e0 >= nnz) return;
    if (e0 + 8 <= nnz) {
        int4 ra = *(const int4*)(er + e0), rb = *(const int4*)(er + e0 + 4);
        int4 ca = *(const int4*)(ec + e0), cb = *(const int4*)(ec + e0 + 4);
        float4 va = *(const float4*)(ev + e0), vb = *(const float4*)(ev + e0 + 4);
        int rr[8] = {ra.x, ra.y, ra.z, ra.w, rb.x, rb.y, rb.z, rb.w};
        int cc[8] = {ca.x, ca.y, ca.z, ca.w, cb.x, cb.y, cb.z, cb.w};
        float vv[8] = {va.x, va.y, va.z, va.w, vb.x, vb.y, vb.z, vb.w};
        float4 x[8];
#pragma unroll
        for (int i = 0; i < 8; i++)
            x[i] = *(const float4*)(g_H1 + (size_t)cc[i] * 64 + l * 4);
#pragma unroll
        for (int i = 0; i < 8; i++)
            red4(g_F2 + (size_t)rr[i] * 64 + l * 4,
                 vv[i] * x[i].x, vv[i] * x[i].y, vv[i] * x[i].z, vv[i] * x[i].w);
    } else {
        for (int e = e0; e < nnz; e++) {
            int r = __ldg(er + e), c = __ldg(ec + e);
            float v = __ldg(ev + e);
            float4 x = *(const float4*)(g_H1 + (size_t)c * 64 + l * 4);
            red4(g_F2 + (size_t)r * 64 + l * 4, v * x.x, v * x.y, v * x.z, v * x.w);
        }
    }
}

// ============================================================================
// Fused MLP head: layer1 (896->64) bf16x3 mma, layers 2/3 FFMA.
// ============================================================================
__global__ __launch_bounds__(256, 2) void k_mlp_mma(
    const int* __restrict__ uIdx, const int* __restrict__ itIdx,
    const float* __restrict__ uE, const float* __restrict__ iE,
    const float* __restrict__ T1b,
    const float* __restrict__ T2W, const float* __restrict__ T2b,
    const float* __restrict__ T3W, const float* __restrict__ T3b,
    float* __restrict__ out, int B)
{
    constexpr int SR = 232;
    constexpr int ABUF = 64 * SR;
    constexpr int OFF_SU = 2 * ABUF * 2;
    constexpr int OFF_SI = OFF_SU + 256;
    constexpr int HSR = 65;
    constexpr int OFF_T2 = 64 * HSR * 4 + 64;
    constexpr int OFF_PART = OFF_T2 + 32 * 64 * 4;
    extern __shared__ __align__(16) char smem[];
    __nv_bfloat16* sA = (__nv_bfloat16*)smem;
    const u32 sbase = smem_u32(smem);
    int* su = (int*)(smem + OFF_SU);
    int* si = (int*)(smem + OFF_SI);

    const int t = threadIdx.x, wid = t >> 5, lane = t & 31;
    const int wm = wid >> 2, wn = wid & 3;
    const int rb = blockIdx.x * 64;

    if (t < 64) {
        int br = rb + t;
        su[t] = (br < B) ? uIdx[br] : 0;
        si[t] = (br < B) ? itIdx[br] : 0;
    }

    float acc[2][2][4];
#pragma unroll
    for (int mt = 0; mt < 2; mt++)
#pragma unroll
        for (int j = 0; j < 2; j++)
#pragma unroll
            for (int q = 0; q < 4; q++) acc[mt][j][q] = 0.f;

    const int arow = lane & 15;
    const int kshift = (lane >> 4) * 8;

    for (int chunk = 0; chunk < 4; chunk++) {
        const int kb = chunk * 224;
        __syncthreads();
#pragma unroll
        for (int it = 0; it < 14; it++) {
            int fid = t + it * 256;
            int r = fid / 56;
            int c4 = (fid % 56) * 4;
            int kg = kb + c4;
            const float* src; int stride, off, rowi;
            if (kg < 256)      { src = uE;   stride = 256; off = kg;       rowi = su[r]; }
            else if (kg < 384) { src = g_F1; stride = 128; off = kg - 256; rowi = su[r]; }
            else if (kg < 448) { src = g_F2; stride = 64;  off = kg - 384; rowi = su[r]; }
            else if (kg < 704) { src = iE;   stride = 256; off = kg - 448; rowi = si[r]; }
            else if (kg < 832) { src = g_F1; stride = 128; off = kg - 704; rowi = si[r] + U_NUM; }
            else               { src = g_F2; stride = 64;  off = kg - 832; rowi = si[r] + U_NUM; }
            float4 v = *(const float4*)(src + (size_t)rowi * stride + off);
            u32 h01, l01, h23, l23;
            split2(v.x, v.y, h01, l01);
            split2(v.z, v.w, h23, l23);
            int so = r * SR + c4;
            *(uint2*)(sA + so)        = make_uint2(h01, h23);
            *(uint2*)(sA + ABUF + so) = make_uint2(l01, l23);
        }
        __syncthreads();

#pragma unroll 2
        for (int ks2 = 0; ks2 < 14; ks2++) {
            const int ks = chunk * 14 + ks2;
            uint4 bw[2];
#pragma unroll
            for (int j = 0; j < 2; j++) {
                int nt = wn * 2 + j;
                bw[j] = __ldg(g_t1f + ((u32)(nt * 56 + ks)) * 32 + lane);
            }
            u32 a[2][2][4];
#pragma unroll
            for (int v = 0; v < 2; v++)
#pragma unroll
                for (int mt = 0; mt < 2; mt++) {
                    int row = wm * 32 + mt * 16 + arow;
                    u32 addr = sbase + (u32)((v * ABUF + row * SR + ks2 * 16 + kshift) * 2);
                    ldm4(a[v][mt], addr);
                }
#pragma unroll
            for (int mt = 0; mt < 2; mt++)
#pragma unroll
                for (int j = 0; j < 2; j++) {
                    mma16816(acc[mt][j], a[0][mt], bw[j].x, bw[j].y);
                    mma16816(acc[mt][j], a[0][mt], bw[j].z, bw[j].w);
                    mma16816(acc[mt][j], a[1][mt], bw[j].x, bw[j].y);
                }
        }
    }
    __syncthreads();

    float* Hs = (float*)smem;
    float* T2s = (float*)(smem + OFF_T2);
    float* part = (float*)(smem + OFF_PART);
    {
        const int rr = wm * 32 + (lane >> 2);
        const int cc = wn * 16 + (lane & 3) * 2;
#pragma unroll
        for (int mt = 0; mt < 2; mt++)
#pragma unroll
            for (int j = 0; j < 2; j++) {
                int c = cc + j * 8;
                float tb0 = __ldg(T1b + c), tb1 = __ldg(T1b + c + 1);
#pragma unroll
                for (int half = 0; half < 2; half++) {
                    int r = rr + mt * 16 + half * 8;
                    Hs[r * HSR + c]     = fmaxf(acc[mt][j][half * 2] + tb0, 0.f);
                    Hs[r * HSR + c + 1] = fmaxf(acc[mt][j][half * 2 + 1] + tb1, 0.f);
                }
            }
    }
#pragma unroll
    for (int i = 0; i < 2; i++) {
        int idx = t + i * 256;
        ((float4*)T2s)[idx] = ((const float4*)T2W)[idx];
    }
    __syncthreads();

    {
        int r = t & 63, g = t >> 6;
        float p = 0.f;
#pragma unroll
        for (int j = 0; j < 8; j++) {
            int c2 = g * 8 + j;
            float s = T2b[c2];
#pragma unroll
            for (int k = 0; k < 64; k++) s += Hs[r * HSR + k] * T2s[c2 * 64 + k];
            p += fmaxf(s, 0.f) * T3W[c2];
        }
        part[g * 64 + r] = p;
    }
    __syncthreads();
    if (t < 64) {
        int br = rb + t;
        if (br < B)
            out[br] = part[t] + part[64 + t] + part[128 + t] + part[192 + t] + T3b[0];
    }
}

// ============================================================================
extern "C" void kernel_launch(void* const* d_in, const int* in_sizes, int n_in,
                              void* d_out, int out_size)
{
    const int*   userIdx = (const int*)d_in[0];
    const int*   itemIdx = (const int*)d_in[1];
    const int*   er      = (const int*)d_in[2];
    const int*   ec      = (const int*)d_in[3];
    const float* ev      = (const float*)d_in[4];
    const float* uE      = (const float*)d_in[5];
    const float* iE      = (const float*)d_in[6];
    const float* W1_0    = (const float*)d_in[7];
    const float* b1_0    = (const float*)d_in[8];
    const float* W2_0    = (const float*)d_in[9];
    const float* b2_0    = (const float*)d_in[10];
    const float* W1_1    = (const float*)d_in[11];
    const float* b1_1    = (const float*)d_in[12];
    const float* W2_1    = (const float*)d_in[13];
    const float* b2_1    = (const float*)d_in[14];
    const float* T1W     = (const float*)d_in[15];
    const float* T1b     = (const float*)d_in[16];
    const float* T2W     = (const float*)d_in[17];
    const float* T2b     = (const float*)d_in[18];
    const float* T3W     = (const float*)d_in[19];
    const float* T3b     = (const float*)d_in[20];
    float* out = (float*)d_out;

    const int B   = in_sizes[0];
    const int nnz = in_sizes[2];

    constexpr int SMEM0 = 2 * 64 * (128 + 8) * 2;    // 34816, OCC=2
    constexpr int SMEM1 = 2 * 64 * (64 + 8) * 2;     // 18432, OCC=4
    constexpr int SMEMM = 2 * 64 * 232 * 2 + 1024;   // 60416, OCC=2
    static bool attr_done = false;
    if (!attr_done) {
        cudaFuncSetAttribute((const void*)k_gemm_mma<256, 2, 64, 128, 256, 128, 0, 2, 4, 4>,
                             cudaFuncAttributeMaxDynamicSharedMemorySize, SMEM0);
        cudaFuncSetAttribute((const void*)k_gemm_mma<128, 4, 64, 64, 128, 64, 1, 2, 2, 4>,
                             cudaFuncAttributeMaxDynamicSharedMemorySize, SMEM1);
        cudaFuncSetAttribute((const void*)k_mlp_mma,
                             cudaFuncAttributeMaxDynamicSharedMemorySize, SMEMM);
        attr_done = true;
    }

    k_prep<<<96, 256>>>(W1_0, W2_0, W1_1, W2_1, T1W);

    k_gemm_mma<256, 2, 64, 128, 256, 128, 0, 2, 4, 4>
        <<<(NTOT + 63) / 64, 256, SMEM0>>>(uE, iE, b1_0, b2_0);

    {
        long long warps = ((long long)nnz + 7) / 8;
        int blocks = (int)((warps * 32 + 255) / 256);
        k_spmm128<<<blocks, 256>>>(er, ec, ev, nnz);
    }

    k_gemm_mma<128, 4, 64, 64, 128, 64, 1, 2, 2, 4>
        <<<(NTOT + 63) / 64, 128, SMEM1>>>(uE, iE, b1_1, b2_1);

    {
        long long hws = ((long long)nnz + 7) / 8;
        int blocks = (int)((hws * 16 + 255) / 256);
        k_spmm64<<<blocks, 256>>>(er, ec, ev, nnz);
    }

    k_mlp_mma<<<(B + 63) / 64, 256, SMEMM>>>(userIdx, itemIdx, uE, iE,
                                             T1b, T2W, T2b, T3W, T3b, out, B);
}